// round 1
// baseline (speedup 1.0000x reference)
#include <cuda_runtime.h>
#include <math.h>

#define Bb 2
#define Dd 256
#define Nn 8192
#define CIc 128
#define Mm 4096

#define TSTR 68   // padded row stride for [c][k] tiles (float4-aligned, conflict-friendly)
#define PSTR 65   // padded row stride for P tile (odd -> conflict-free column reads)

// -------- scratch (static device globals; no runtime allocation) --------
__device__ float d_theta[Bb*CIc*Nn];   // (B, CI, N)
__device__ float d_gp[Bb*CIc*Mm];      // pooled g   (B, CI, M)
__device__ float d_php[Bb*CIc*Mm];     // pooled phi (B, CI, M)
__device__ float d_y[Bb*CIc*Nn];       // attention output (B, CI, N)
__device__ float d_Wy[Bb*Dd*Nn];       // W conv output (B, D, N)
__device__ float d_stats[2*Dd];        // per-channel mean, inv_std

// ============================================================================
// Kernel 1: the three 1x1-conv projections. C(128 x N) = W(128 x 256) @ f(256 x N) + b
// grid (N/64, B, 3); z selects theta / g / phi; g & phi are maxpool2-fused.
// Tile: BM=128 (all CI), BN=64, BK=32. 256 threads, 8x4 microtile.
// ============================================================================
__global__ __launch_bounds__(256) void proj_kernel(
    const float* __restrict__ f,
    const float* __restrict__ gw, const float* __restrict__ gb,
    const float* __restrict__ tw, const float* __restrict__ tb,
    const float* __restrict__ pw, const float* __restrict__ pb)
{
    const int zi = blockIdx.z;
    const float* W  = (zi == 0) ? tw : (zi == 1) ? gw : pw;
    const float* bs = (zi == 0) ? tb : (zi == 1) ? gb : pb;
    float* out      = (zi == 0) ? d_theta : (zi == 1) ? d_gp : d_php;

    const int b   = blockIdx.y;
    const int n0  = blockIdx.x * 64;
    const int tid = threadIdx.x;
    const int tx  = tid & 15, ty = tid >> 4;

    __shared__ float w_sm[32][132];   // [d][c]
    __shared__ float f_sm[32][TSTR];  // [d][n]

    float acc[8][4];
    #pragma unroll
    for (int i = 0; i < 8; i++)
        #pragma unroll
        for (int j = 0; j < 4; j++) acc[i][j] = 0.f;

    const float* fb = f + (size_t)b * Dd * Nn;

    for (int d0 = 0; d0 < Dd; d0 += 32) {
        #pragma unroll
        for (int r = 0; r < 16; r++) {               // 128c x 32d weight tile
            int idx = tid + r * 256;
            int c = idx >> 5, dd2 = idx & 31;
            w_sm[dd2][c] = W[c * Dd + d0 + dd2];
        }
        #pragma unroll
        for (int r = 0; r < 2; r++) {                // 32d x 64n f tile (float4)
            int idx = (tid + r * 256) * 4;
            int dd2 = idx >> 6, nn2 = idx & 63;
            *(float4*)&f_sm[dd2][nn2] =
                *(const float4*)&fb[(size_t)(d0 + dd2) * Nn + n0 + nn2];
        }
        __syncthreads();
        #pragma unroll
        for (int dd2 = 0; dd2 < 32; dd2++) {
            float a[8];
            float4 a0 = *(float4*)&w_sm[dd2][ty * 8];
            float4 a1 = *(float4*)&w_sm[dd2][ty * 8 + 4];
            a[0]=a0.x; a[1]=a0.y; a[2]=a0.z; a[3]=a0.w;
            a[4]=a1.x; a[5]=a1.y; a[6]=a1.z; a[7]=a1.w;
            float4 bv = *(float4*)&f_sm[dd2][tx * 4];
            float bbv[4] = {bv.x, bv.y, bv.z, bv.w};
            #pragma unroll
            for (int i = 0; i < 8; i++)
                #pragma unroll
                for (int j = 0; j < 4; j++)
                    acc[i][j] = fmaf(a[i], bbv[j], acc[i][j]);
        }
        __syncthreads();
    }

    if (zi == 0) {  // theta: direct store
        #pragma unroll
        for (int i = 0; i < 8; i++) {
            int c = ty * 8 + i;
            float bias = bs[c];
            float4 v = make_float4(acc[i][0] + bias, acc[i][1] + bias,
                                   acc[i][2] + bias, acc[i][3] + bias);
            *(float4*)&out[((size_t)b * CIc + c) * Nn + n0 + tx * 4] = v;
        }
    } else {        // g / phi: fused maxpool2 (bias is per-channel const: max commutes)
        #pragma unroll
        for (int i = 0; i < 8; i++) {
            int c = ty * 8 + i;
            float bias = bs[c];
            float2 v = make_float2(fmaxf(acc[i][0], acc[i][1]) + bias,
                                   fmaxf(acc[i][2], acc[i][3]) + bias);
            *(float2*)&out[((size_t)b * CIc + c) * Mm + (n0 >> 1) + tx * 2] = v;
        }
    }
}

// ============================================================================
// Kernel 2: streaming attention (single pass, no max-subtraction needed:
// logits max ~21 -> exp safe in fp32).  Per block: 64 queries x all 4096 keys.
// GEMM1: S(64q x 64k) = theta_tile^T . phi_tile ; P = exp(S) -> smem
// GEMM2: yacc(128c x 64q) += g_tile . P^T ; l[q] += rowsum(P)
// ============================================================================
__global__ __launch_bounds__(256) void attn_kernel()
{
    extern __shared__ float sm[];
    float* theta_sm = sm;                       // [128][TSTR]
    float* phi_sm   = theta_sm + 128 * TSTR;    // [128][TSTR]
    float* g_sm     = phi_sm   + 128 * TSTR;    // [128][TSTR]
    float* P_sm     = g_sm     + 128 * TSTR;    // [64][PSTR]
    float* l_sm     = P_sm     + 64 * PSTR;     // [64]

    const int b   = blockIdx.y;
    const int q0g = blockIdx.x * 64;
    const int tid = threadIdx.x;
    const int tx  = tid & 15, ty = tid >> 4;

    const float* theta = d_theta + (size_t)b * CIc * Nn;
    const float* phi   = d_php   + (size_t)b * CIc * Mm;
    const float* g     = d_gp    + (size_t)b * CIc * Mm;

    #pragma unroll
    for (int r = 0; r < 8; r++) {               // theta tile 128c x 64q
        int idx = (tid + r * 256) * 4;
        int c = idx >> 6, qq = idx & 63;
        *(float4*)&theta_sm[c * TSTR + qq] =
            *(const float4*)&theta[(size_t)c * Nn + q0g + qq];
    }
    if (tid < 64) l_sm[tid] = 0.f;

    float yacc[8][4];
    #pragma unroll
    for (int i = 0; i < 8; i++)
        #pragma unroll
        for (int j = 0; j < 4; j++) yacc[i][j] = 0.f;

    for (int k0 = 0; k0 < Mm; k0 += 64) {
        __syncthreads();                         // prev GEMM2 done before overwrite
        #pragma unroll
        for (int r = 0; r < 8; r++) {            // phi & g tiles 128c x 64k
            int idx = (tid + r * 256) * 4;
            int c = idx >> 6, kk = idx & 63;
            *(float4*)&phi_sm[c * TSTR + kk] = *(const float4*)&phi[(size_t)c * Mm + k0 + kk];
            *(float4*)&g_sm[c * TSTR + kk]   = *(const float4*)&g  [(size_t)c * Mm + k0 + kk];
        }
        __syncthreads();

        // ---- GEMM1: scores, thread = 4q x 4k ----
        float s[4][4];
        #pragma unroll
        for (int i = 0; i < 4; i++)
            #pragma unroll
            for (int j = 0; j < 4; j++) s[i][j] = 0.f;

        #pragma unroll 8
        for (int c = 0; c < CIc; c++) {
            float4 av = *(float4*)&theta_sm[c * TSTR + ty * 4];
            float4 bv = *(float4*)&phi_sm[c * TSTR + tx * 4];
            float aa[4] = {av.x, av.y, av.z, av.w};
            float bb2[4] = {bv.x, bv.y, bv.z, bv.w};
            #pragma unroll
            for (int i = 0; i < 4; i++)
                #pragma unroll
                for (int j = 0; j < 4; j++)
                    s[i][j] = fmaf(aa[i], bb2[j], s[i][j]);
        }

        // ---- exp, P store, l partial (reduce over 16-lane tx groups) ----
        #pragma unroll
        for (int i = 0; i < 4; i++) {
            float w0 = __expf(s[i][0]);
            float w1 = __expf(s[i][1]);
            float w2 = __expf(s[i][2]);
            float w3 = __expf(s[i][3]);
            int q = ty * 4 + i;
            P_sm[q * PSTR + tx * 4 + 0] = w0;
            P_sm[q * PSTR + tx * 4 + 1] = w1;
            P_sm[q * PSTR + tx * 4 + 2] = w2;
            P_sm[q * PSTR + tx * 4 + 3] = w3;
            float lp = (w0 + w1) + (w2 + w3);
            lp += __shfl_xor_sync(0xffffffffu, lp, 8);
            lp += __shfl_xor_sync(0xffffffffu, lp, 4);
            lp += __shfl_xor_sync(0xffffffffu, lp, 2);
            lp += __shfl_xor_sync(0xffffffffu, lp, 1);
            if (tx == 0) l_sm[q] += lp;
        }
        __syncthreads();

        // ---- GEMM2: yacc += g . P^T, thread = 8c x 4q ----
        #pragma unroll 4
        for (int k = 0; k < 64; k++) {
            float pv[4], gv[8];
            #pragma unroll
            for (int j = 0; j < 4; j++) pv[j] = P_sm[(tx * 4 + j) * PSTR + k];
            #pragma unroll
            for (int i = 0; i < 8; i++) gv[i] = g_sm[(ty * 8 + i) * TSTR + k];
            #pragma unroll
            for (int i = 0; i < 8; i++)
                #pragma unroll
                for (int j = 0; j < 4; j++)
                    yacc[i][j] = fmaf(gv[i], pv[j], yacc[i][j]);
        }
    }

    float inv[4];
    #pragma unroll
    for (int j = 0; j < 4; j++) inv[j] = 1.f / l_sm[tx * 4 + j];
    #pragma unroll
    for (int i = 0; i < 8; i++) {
        int c = ty * 8 + i;
        float4 v = make_float4(yacc[i][0] * inv[0], yacc[i][1] * inv[1],
                               yacc[i][2] * inv[2], yacc[i][3] * inv[3]);
        *(float4*)&d_y[((size_t)b * CIc + c) * Nn + q0g + tx * 4] = v;
    }
}

// ============================================================================
// Kernel 3: W 1x1 conv: Wy(256 x N) = Ww(256 x 128) @ y(128 x N) + Wb
// grid (N/64, D/128, B)
// ============================================================================
__global__ __launch_bounds__(256) void wconv_kernel(
    const float* __restrict__ Ww, const float* __restrict__ Wb)
{
    const int b    = blockIdx.z;
    const int dblk = blockIdx.y * 128;
    const int n0   = blockIdx.x * 64;
    const int tid  = threadIdx.x;
    const int tx   = tid & 15, ty = tid >> 4;

    __shared__ float w_sm[32][132];
    __shared__ float y_sm[32][TSTR];

    float acc[8][4];
    #pragma unroll
    for (int i = 0; i < 8; i++)
        #pragma unroll
        for (int j = 0; j < 4; j++) acc[i][j] = 0.f;

    const float* yb = d_y + (size_t)b * CIc * Nn;

    for (int c0 = 0; c0 < CIc; c0 += 32) {
        #pragma unroll
        for (int r = 0; r < 16; r++) {
            int idx = tid + r * 256;
            int dl = idx >> 5, cc = idx & 31;
            w_sm[cc][dl] = Ww[(size_t)(dblk + dl) * CIc + c0 + cc];
        }
        #pragma unroll
        for (int r = 0; r < 2; r++) {
            int idx = (tid + r * 256) * 4;
            int cc = idx >> 6, nn2 = idx & 63;
            *(float4*)&y_sm[cc][nn2] =
                *(const float4*)&yb[(size_t)(c0 + cc) * Nn + n0 + nn2];
        }
        __syncthreads();
        #pragma unroll
        for (int cc = 0; cc < 32; cc++) {
            float a[8];
            float4 a0 = *(float4*)&w_sm[cc][ty * 8];
            float4 a1 = *(float4*)&w_sm[cc][ty * 8 + 4];
            a[0]=a0.x; a[1]=a0.y; a[2]=a0.z; a[3]=a0.w;
            a[4]=a1.x; a[5]=a1.y; a[6]=a1.z; a[7]=a1.w;
            float4 bv = *(float4*)&y_sm[cc][tx * 4];
            float bbv[4] = {bv.x, bv.y, bv.z, bv.w};
            #pragma unroll
            for (int i = 0; i < 8; i++)
                #pragma unroll
                for (int j = 0; j < 4; j++)
                    acc[i][j] = fmaf(a[i], bbv[j], acc[i][j]);
        }
        __syncthreads();
    }

    #pragma unroll
    for (int i = 0; i < 8; i++) {
        int d = dblk + ty * 8 + i;
        float bias = Wb[d];
        float4 v = make_float4(acc[i][0] + bias, acc[i][1] + bias,
                               acc[i][2] + bias, acc[i][3] + bias);
        *(float4*)&d_Wy[((size_t)b * Dd + d) * Nn + n0 + tx * 4] = v;
    }
}

// ============================================================================
// Kernel 4: per-channel BN stats over (B, N), double accumulation. grid = D
// ============================================================================
__global__ __launch_bounds__(256) void stats_kernel()
{
    __shared__ double sh[256];
    __shared__ double sh2[256];
    const int d = blockIdx.x, tid = threadIdx.x;
    double s = 0.0, ss = 0.0;
    for (int b = 0; b < Bb; b++) {
        const float* p = d_Wy + ((size_t)b * Dd + d) * Nn;
        for (int n = tid; n < Nn; n += 256) {
            double v = (double)p[n];
            s += v; ss += v * v;
        }
    }
    sh[tid] = s; sh2[tid] = ss;
    __syncthreads();
    for (int o = 128; o > 0; o >>= 1) {
        if (tid < o) { sh[tid] += sh[tid + o]; sh2[tid] += sh2[tid + o]; }
        __syncthreads();
    }
    if (tid == 0) {
        double cnt  = (double)(Bb * Nn);
        double mean = sh[0] / cnt;
        double var  = sh2[0] / cnt - mean * mean;   // biased, like torch BN
        d_stats[d]      = (float)mean;
        d_stats[Dd + d] = (float)(1.0 / sqrt(var + 1e-5));
    }
}

// ============================================================================
// Kernel 5: normalize + affine + residual, float4 elementwise
// ============================================================================
__global__ __launch_bounds__(256) void final_kernel(
    const float* __restrict__ f, const float* __restrict__ gamma,
    const float* __restrict__ beta, float* __restrict__ out)
{
    size_t i4 = (size_t)blockIdx.x * 256 + threadIdx.x;
    size_t i  = i4 * 4;
    int d = (int)((i / Nn) % Dd);
    float mean = d_stats[d];
    float inv  = d_stats[Dd + d];
    float gm = gamma[d] * inv;
    float bt = beta[d] - mean * gm;
    float4 w  = *(const float4*)&d_Wy[i];
    float4 fv = *(const float4*)&f[i];
    float4 o;
    o.x = fmaf(w.x, gm, bt) + fv.x;
    o.y = fmaf(w.y, gm, bt) + fv.y;
    o.z = fmaf(w.z, gm, bt) + fv.z;
    o.w = fmaf(w.w, gm, bt) + fv.w;
    *(float4*)&out[i] = o;
}

// ============================================================================
extern "C" void kernel_launch(void* const* d_in, const int* in_sizes, int n_in,
                              void* d_out, int out_size)
{
    const float* f   = (const float*)d_in[0];
    const float* gw  = (const float*)d_in[1];
    const float* gb  = (const float*)d_in[2];
    const float* tw  = (const float*)d_in[3];
    const float* tb  = (const float*)d_in[4];
    const float* pw  = (const float*)d_in[5];
    const float* pb  = (const float*)d_in[6];
    const float* Ww  = (const float*)d_in[7];
    const float* Wb  = (const float*)d_in[8];
    const float* gma = (const float*)d_in[9];
    const float* bta = (const float*)d_in[10];
    float* out = (float*)d_out;

    proj_kernel<<<dim3(Nn / 64, Bb, 3), 256>>>(f, gw, gb, tw, tb, pw, pb);

    size_t smem = (size_t)(3 * 128 * TSTR + 64 * PSTR + 64) * sizeof(float);
    cudaFuncSetAttribute(attn_kernel, cudaFuncAttributeMaxDynamicSharedMemorySize,
                         (int)smem);
    attn_kernel<<<dim3(Nn / 64, Bb), 256, smem>>>();

    wconv_kernel<<<dim3(Nn / 64, Dd / 128, Bb), 256>>>(Ww, Wb);
    stats_kernel<<<Dd, 256>>>();
    final_kernel<<<(Bb * Dd * Nn) / (256 * 4), 256>>>(f, gma, bta, out);
}

// round 2
// speedup vs baseline: 2.9064x; 2.9064x over previous
#include <cuda_runtime.h>
#include <math.h>
#include <stdint.h>

#define Bb 2
#define Dd 256
#define Nn 8192
#define CIc 128
#define Mm 4096

#define TSTR 68   // padded row stride for [c][k] tiles in SIMT kernels
// attention smem strides (chosen for conflict-free mma fragment access)
#define THSTR 132 // theta [q][c]   : (4*grp + tig) mod 32 distinct
#define KSTR  72  // phi/g [c][k]   : (8*tig + grp) / (8*grp + tig) distinct
#define PSTR  68  // P     [q][k]   : (4*grp + tig) distinct

// -------- scratch (static device globals; no runtime allocation) --------
__device__ float  d_theta[Bb*CIc*Nn];   // (B, CI, N)
__device__ float  d_gp[Bb*CIc*Mm];      // pooled g   (B, CI, M)
__device__ float  d_php[Bb*CIc*Mm];     // pooled phi (B, CI, M)
__device__ float  d_y[Bb*CIc*Nn];       // attention output (B, CI, N)
__device__ float  d_Wy[Bb*Dd*Nn];       // W conv output (B, D, N)
__device__ double d_acc[2*Dd];          // BN sum / sumsq accumulators
__device__ float  d_stats[2*Dd];        // per-channel mean, inv_std

// ---------------- helpers ----------------
__device__ __forceinline__ float tf32r(float x) {
    uint32_t u;
    asm("cvt.rna.tf32.f32 %0, %1;" : "=r"(u) : "f"(x));
    return __uint_as_float(u);
}

__device__ __forceinline__ void mma_tf32(float* d, const uint32_t* a,
                                         uint32_t b0, uint32_t b1) {
    asm volatile(
        "mma.sync.aligned.m16n8k8.row.col.f32.tf32.tf32.f32 "
        "{%0,%1,%2,%3},{%4,%5,%6,%7},{%8,%9},{%0,%1,%2,%3};"
        : "+f"(d[0]), "+f"(d[1]), "+f"(d[2]), "+f"(d[3])
        : "r"(a[0]), "r"(a[1]), "r"(a[2]), "r"(a[3]), "r"(b0), "r"(b1));
}

// ============================================================================
// Kernel 1: three 1x1-conv projections. C(128 x N) = W(128 x 256) @ f + b
// z selects theta / g / phi; g & phi are maxpool2-fused.
// ============================================================================
__global__ __launch_bounds__(256) void proj_kernel(
    const float* __restrict__ f,
    const float* __restrict__ gw, const float* __restrict__ gb,
    const float* __restrict__ tw, const float* __restrict__ tb,
    const float* __restrict__ pw, const float* __restrict__ pb)
{
    const int zi = blockIdx.z;
    const float* W  = (zi == 0) ? tw : (zi == 1) ? gw : pw;
    const float* bs = (zi == 0) ? tb : (zi == 1) ? gb : pb;
    float* out      = (zi == 0) ? d_theta : (zi == 1) ? d_gp : d_php;

    const int b   = blockIdx.y;
    const int n0  = blockIdx.x * 64;
    const int tid = threadIdx.x;
    const int tx  = tid & 15, ty = tid >> 4;

    __shared__ float w_sm[32][132];   // [d][c]
    __shared__ float f_sm[32][TSTR];  // [d][n]

    float acc[8][4];
    #pragma unroll
    for (int i = 0; i < 8; i++)
        #pragma unroll
        for (int j = 0; j < 4; j++) acc[i][j] = 0.f;

    const float* fb = f + (size_t)b * Dd * Nn;

    for (int d0 = 0; d0 < Dd; d0 += 32) {
        #pragma unroll
        for (int r = 0; r < 16; r++) {
            int idx = tid + r * 256;
            int c = idx >> 5, dd2 = idx & 31;
            w_sm[dd2][c] = W[c * Dd + d0 + dd2];
        }
        #pragma unroll
        for (int r = 0; r < 2; r++) {
            int idx = (tid + r * 256) * 4;
            int dd2 = idx >> 6, nn2 = idx & 63;
            *(float4*)&f_sm[dd2][nn2] =
                *(const float4*)&fb[(size_t)(d0 + dd2) * Nn + n0 + nn2];
        }
        __syncthreads();
        #pragma unroll
        for (int dd2 = 0; dd2 < 32; dd2++) {
            float a[8];
            float4 a0 = *(float4*)&w_sm[dd2][ty * 8];
            float4 a1 = *(float4*)&w_sm[dd2][ty * 8 + 4];
            a[0]=a0.x; a[1]=a0.y; a[2]=a0.z; a[3]=a0.w;
            a[4]=a1.x; a[5]=a1.y; a[6]=a1.z; a[7]=a1.w;
            float4 bv = *(float4*)&f_sm[dd2][tx * 4];
            float bbv[4] = {bv.x, bv.y, bv.z, bv.w};
            #pragma unroll
            for (int i = 0; i < 8; i++)
                #pragma unroll
                for (int j = 0; j < 4; j++)
                    acc[i][j] = fmaf(a[i], bbv[j], acc[i][j]);
        }
        __syncthreads();
    }

    if (zi == 0) {
        #pragma unroll
        for (int i = 0; i < 8; i++) {
            int c = ty * 8 + i;
            float bias = bs[c];
            float4 v = make_float4(acc[i][0] + bias, acc[i][1] + bias,
                                   acc[i][2] + bias, acc[i][3] + bias);
            *(float4*)&out[((size_t)b * CIc + c) * Nn + n0 + tx * 4] = v;
        }
    } else {
        #pragma unroll
        for (int i = 0; i < 8; i++) {
            int c = ty * 8 + i;
            float bias = bs[c];
            float2 v = make_float2(fmaxf(acc[i][0], acc[i][1]) + bias,
                                   fmaxf(acc[i][2], acc[i][3]) + bias);
            *(float2*)&out[((size_t)b * CIc + c) * Mm + (n0 >> 1) + tx * 2] = v;
        }
    }
}

// ============================================================================
// Kernel 2: tensor-core attention (tf32 mma.sync m16n8k8).
// CTA: 128 queries x all 4096 keys (64-key chunks). 8 warps.
// GEMM1 roles: warp = (wq1 = w&3 -> 32q, wk1 = w>>2 -> 32k)
// GEMM2 roles: warp = (wq2 = w&3 -> 32q, wc  = w>>2 -> 64c)
// Single pass: logits max ~21 -> exp safe in fp32, no max subtraction.
// ============================================================================
__global__ __launch_bounds__(256, 1) void attn_kernel()
{
    extern __shared__ float sm[];
    float* th = sm;                     // [128 q][THSTR]  theta (tf32)
    float* ph = th + 128 * THSTR;       // [128 c][KSTR]   phi tile (tf32)
    float* gg = ph + CIc * KSTR;        // [128 c][KSTR]   g tile (tf32)
    float* Pm = gg + CIc * KSTR;        // [128 q][PSTR]   exp(S) (tf32)
    float* l2 = Pm + 128 * PSTR;        // [2][128]        partial row sums

    const uint32_t* thu = (const uint32_t*)th;
    const uint32_t* phu = (const uint32_t*)ph;
    const uint32_t* ggu = (const uint32_t*)gg;
    const uint32_t* Pmu = (const uint32_t*)Pm;

    const int b    = blockIdx.y;
    const int q0g  = blockIdx.x * 128;
    const int tid  = threadIdx.x;
    const int warp = tid >> 5;
    const int lane = tid & 31;
    const int grp  = lane >> 2;
    const int tig  = lane & 3;

    const int wq1 = warp & 3, wk1 = warp >> 2;
    const int Q1 = wq1 * 32, K1 = wk1 * 32;
    const int wq2 = warp & 3, wc = warp >> 2;
    const int Q2 = wq2 * 32, C2 = wc * 64;

    const float* theta = d_theta + (size_t)b * CIc * Nn;
    const float* phi   = d_php   + (size_t)b * CIc * Mm;
    const float* g     = d_gp    + (size_t)b * CIc * Mm;

    // prologue: theta tile 128c x 128q, transposed to [q][c], tf32-rounded
    #pragma unroll
    for (int r = 0; r < 16; r++) {
        int idx = (tid + r * 256) * 4;
        int c = idx >> 7, q = idx & 127;
        float4 v = *(const float4*)&theta[(size_t)c * Nn + q0g + q];
        th[(q + 0) * THSTR + c] = tf32r(v.x);
        th[(q + 1) * THSTR + c] = tf32r(v.y);
        th[(q + 2) * THSTR + c] = tf32r(v.z);
        th[(q + 3) * THSTR + c] = tf32r(v.w);
    }
    l2[tid & 255] = 0.f;   // 256 entries

    float yacc[2][8][4];
    #pragma unroll
    for (int mt = 0; mt < 2; mt++)
        #pragma unroll
        for (int nt = 0; nt < 8; nt++)
            #pragma unroll
            for (int r = 0; r < 4; r++) yacc[mt][nt][r] = 0.f;

    for (int k0 = 0; k0 < Mm; k0 += 64) {
        __syncthreads();   // prev GEMM2 done reading ph/gg/Pm

        #pragma unroll
        for (int r = 0; r < 8; r++) {   // phi & g tiles 128c x 64k
            int idx = (tid + r * 256) * 4;
            int c = idx >> 6, k = idx & 63;
            float4 v = *(const float4*)&phi[(size_t)c * Mm + k0 + k];
            ph[c * KSTR + k + 0] = tf32r(v.x);
            ph[c * KSTR + k + 1] = tf32r(v.y);
            ph[c * KSTR + k + 2] = tf32r(v.z);
            ph[c * KSTR + k + 3] = tf32r(v.w);
            float4 u = *(const float4*)&g[(size_t)c * Mm + k0 + k];
            gg[c * KSTR + k + 0] = tf32r(u.x);
            gg[c * KSTR + k + 1] = tf32r(u.y);
            gg[c * KSTR + k + 2] = tf32r(u.z);
            gg[c * KSTR + k + 3] = tf32r(u.w);
        }
        __syncthreads();

        // ---- GEMM1: S[32q x 32k] = theta^T . phi over CI=128 ----
        float s[2][4][4];
        #pragma unroll
        for (int mt = 0; mt < 2; mt++)
            #pragma unroll
            for (int nt = 0; nt < 4; nt++)
                #pragma unroll
                for (int r = 0; r < 4; r++) s[mt][nt][r] = 0.f;

        #pragma unroll
        for (int c8 = 0; c8 < 16; c8++) {
            const int col = c8 * 8 + tig;
            uint32_t A[2][4];
            #pragma unroll
            for (int mt = 0; mt < 2; mt++) {
                int rb = Q1 + mt * 16 + grp;
                A[mt][0] = thu[(rb    ) * THSTR + col    ];
                A[mt][1] = thu[(rb + 8) * THSTR + col    ];
                A[mt][2] = thu[(rb    ) * THSTR + col + 4];
                A[mt][3] = thu[(rb + 8) * THSTR + col + 4];
            }
            #pragma unroll
            for (int nt = 0; nt < 4; nt++) {
                uint32_t b0 = phu[(col    ) * KSTR + K1 + nt * 8 + grp];
                uint32_t b1 = phu[(col + 4) * KSTR + K1 + nt * 8 + grp];
                mma_tf32(s[0][nt], A[0], b0, b1);
                mma_tf32(s[1][nt], A[1], b0, b1);
            }
        }

        // ---- exp -> Pm (tf32), accumulate row sums ----
        #pragma unroll
        for (int mt = 0; mt < 2; mt++) {
            #pragma unroll
            for (int h = 0; h < 2; h++) {
                int q = Q1 + mt * 16 + grp + 8 * h;
                float lp = 0.f;
                #pragma unroll
                for (int nt = 0; nt < 4; nt++) {
                    float w0 = tf32r(__expf(s[mt][nt][2 * h    ]));
                    float w1 = tf32r(__expf(s[mt][nt][2 * h + 1]));
                    *(float2*)&Pm[q * PSTR + K1 + nt * 8 + 2 * tig] =
                        make_float2(w0, w1);
                    lp += w0 + w1;
                }
                lp += __shfl_xor_sync(0xffffffffu, lp, 1);
                lp += __shfl_xor_sync(0xffffffffu, lp, 2);
                if (tig == 0) l2[wk1 * 128 + q] += lp;
            }
        }
        __syncthreads();

        // ---- GEMM2: Y[32q x 64c] += P[32q x 64k] . g^T[64k x 64c] ----
        #pragma unroll
        for (int kk = 0; kk < 8; kk++) {
            const int kcol = kk * 8 + tig;
            uint32_t A[2][4];
            #pragma unroll
            for (int mt = 0; mt < 2; mt++) {
                int rb = Q2 + mt * 16 + grp;
                A[mt][0] = Pmu[(rb    ) * PSTR + kcol    ];
                A[mt][1] = Pmu[(rb + 8) * PSTR + kcol    ];
                A[mt][2] = Pmu[(rb    ) * PSTR + kcol + 4];
                A[mt][3] = Pmu[(rb + 8) * PSTR + kcol + 4];
            }
            #pragma unroll
            for (int nt = 0; nt < 8; nt++) {
                uint32_t b0 = ggu[(C2 + nt * 8 + grp) * KSTR + kcol    ];
                uint32_t b1 = ggu[(C2 + nt * 8 + grp) * KSTR + kcol + 4];
                mma_tf32(yacc[0][nt], A[0], b0, b1);
                mma_tf32(yacc[1][nt], A[1], b0, b1);
            }
        }
    }

    __syncthreads();
    if (tid < 128) l2[tid] = 1.f / (l2[tid] + l2[128 + tid]);
    __syncthreads();

    float* yb = d_y + (size_t)b * CIc * Nn;
    #pragma unroll
    for (int mt = 0; mt < 2; mt++) {
        int q_lo = Q2 + mt * 16 + grp;
        int q_hi = q_lo + 8;
        float ilo = l2[q_lo], ihi = l2[q_hi];
        #pragma unroll
        for (int nt = 0; nt < 8; nt++) {
            int c0 = C2 + nt * 8 + 2 * tig;
            yb[(size_t)(c0    ) * Nn + q0g + q_lo] = yacc[mt][nt][0] * ilo;
            yb[(size_t)(c0 + 1) * Nn + q0g + q_lo] = yacc[mt][nt][1] * ilo;
            yb[(size_t)(c0    ) * Nn + q0g + q_hi] = yacc[mt][nt][2] * ihi;
            yb[(size_t)(c0 + 1) * Nn + q0g + q_hi] = yacc[mt][nt][3] * ihi;
        }
    }
}

// ============================================================================
// Kernel 3: W 1x1 conv: Wy(256 x N) = Ww(256 x 128) @ y(128 x N) + Wb
// ============================================================================
__global__ __launch_bounds__(256) void wconv_kernel(
    const float* __restrict__ Ww, const float* __restrict__ Wb)
{
    const int b    = blockIdx.z;
    const int dblk = blockIdx.y * 128;
    const int n0   = blockIdx.x * 64;
    const int tid  = threadIdx.x;
    const int tx   = tid & 15, ty = tid >> 4;

    __shared__ float w_sm[32][132];
    __shared__ float y_sm[32][TSTR];

    float acc[8][4];
    #pragma unroll
    for (int i = 0; i < 8; i++)
        #pragma unroll
        for (int j = 0; j < 4; j++) acc[i][j] = 0.f;

    const float* yb = d_y + (size_t)b * CIc * Nn;

    for (int c0 = 0; c0 < CIc; c0 += 32) {
        #pragma unroll
        for (int r = 0; r < 16; r++) {
            int idx = tid + r * 256;
            int dl = idx >> 5, cc = idx & 31;
            w_sm[cc][dl] = Ww[(size_t)(dblk + dl) * CIc + c0 + cc];
        }
        #pragma unroll
        for (int r = 0; r < 2; r++) {
            int idx = (tid + r * 256) * 4;
            int cc = idx >> 6, nn2 = idx & 63;
            *(float4*)&y_sm[cc][nn2] =
                *(const float4*)&yb[(size_t)(c0 + cc) * Nn + n0 + nn2];
        }
        __syncthreads();
        #pragma unroll
        for (int cc = 0; cc < 32; cc++) {
            float a[8];
            float4 a0 = *(float4*)&w_sm[cc][ty * 8];
            float4 a1 = *(float4*)&w_sm[cc][ty * 8 + 4];
            a[0]=a0.x; a[1]=a0.y; a[2]=a0.z; a[3]=a0.w;
            a[4]=a1.x; a[5]=a1.y; a[6]=a1.z; a[7]=a1.w;
            float4 bv = *(float4*)&y_sm[cc][tx * 4];
            float bbv[4] = {bv.x, bv.y, bv.z, bv.w};
            #pragma unroll
            for (int i = 0; i < 8; i++)
                #pragma unroll
                for (int j = 0; j < 4; j++)
                    acc[i][j] = fmaf(a[i], bbv[j], acc[i][j]);
        }
        __syncthreads();
    }

    #pragma unroll
    for (int i = 0; i < 8; i++) {
        int d = dblk + ty * 8 + i;
        float bias = Wb[d];
        float4 v = make_float4(acc[i][0] + bias, acc[i][1] + bias,
                               acc[i][2] + bias, acc[i][3] + bias);
        *(float4*)&d_Wy[((size_t)b * Dd + d) * Nn + n0 + tx * 4] = v;
    }
}

// ============================================================================
// Kernel 4a/4b/4c: BN stats — zero, accumulate (512 blocks), finalize
// ============================================================================
__global__ void zero_acc_kernel()
{
    if (threadIdx.x < 2 * Dd) d_acc[threadIdx.x] = 0.0;
}

__global__ __launch_bounds__(256) void stats_kernel()
{
    __shared__ double sh[256], sh2[256];
    const int d = blockIdx.x, b = blockIdx.y, tid = threadIdx.x;
    const float4* p = (const float4*)(d_Wy + ((size_t)b * Dd + d) * Nn);
    double s = 0.0, ss = 0.0;
    #pragma unroll
    for (int r = 0; r < 8; r++) {
        float4 v = p[tid + r * 256];
        s  += (double)v.x + (double)v.y + (double)v.z + (double)v.w;
        ss += (double)v.x * v.x + (double)v.y * v.y
            + (double)v.z * v.z + (double)v.w * v.w;
    }
    sh[tid] = s; sh2[tid] = ss;
    __syncthreads();
    for (int o = 128; o > 0; o >>= 1) {
        if (tid < o) { sh[tid] += sh[tid + o]; sh2[tid] += sh2[tid + o]; }
        __syncthreads();
    }
    if (tid == 0) {
        atomicAdd(&d_acc[d],      sh[0]);
        atomicAdd(&d_acc[Dd + d], sh2[0]);
    }
}

__global__ void finalize_kernel()
{
    int d = threadIdx.x;
    if (d < Dd) {
        double cnt  = (double)(Bb * Nn);
        double mean = d_acc[d] / cnt;
        double var  = d_acc[Dd + d] / cnt - mean * mean;
        d_stats[d]      = (float)mean;
        d_stats[Dd + d] = (float)(1.0 / sqrt(var + 1e-5));
    }
}

// ============================================================================
// Kernel 5: normalize + affine + residual
// ============================================================================
__global__ __launch_bounds__(256) void final_kernel(
    const float* __restrict__ f, const float* __restrict__ gamma,
    const float* __restrict__ beta, float* __restrict__ out)
{
    size_t i4 = (size_t)blockIdx.x * 256 + threadIdx.x;
    size_t i  = i4 * 4;
    int d = (int)((i / Nn) % Dd);
    float mean = d_stats[d];
    float inv  = d_stats[Dd + d];
    float gm = gamma[d] * inv;
    float bt = beta[d] - mean * gm;
    float4 w  = *(const float4*)&d_Wy[i];
    float4 fv = *(const float4*)&f[i];
    float4 o;
    o.x = fmaf(w.x, gm, bt) + fv.x;
    o.y = fmaf(w.y, gm, bt) + fv.y;
    o.z = fmaf(w.z, gm, bt) + fv.z;
    o.w = fmaf(w.w, gm, bt) + fv.w;
    *(float4*)&out[i] = o;
}

// ============================================================================
extern "C" void kernel_launch(void* const* d_in, const int* in_sizes, int n_in,
                              void* d_out, int out_size)
{
    const float* f   = (const float*)d_in[0];
    const float* gw  = (const float*)d_in[1];
    const float* gb  = (const float*)d_in[2];
    const float* tw  = (const float*)d_in[3];
    const float* tb  = (const float*)d_in[4];
    const float* pw  = (const float*)d_in[5];
    const float* pb  = (const float*)d_in[6];
    const float* Ww  = (const float*)d_in[7];
    const float* Wb  = (const float*)d_in[8];
    const float* gma = (const float*)d_in[9];
    const float* bta = (const float*)d_in[10];
    float* out = (float*)d_out;

    proj_kernel<<<dim3(Nn / 64, Bb, 3), 256>>>(f, gw, gb, tw, tb, pw, pb);

    size_t smem = (size_t)(128 * THSTR + 2 * CIc * KSTR + 128 * PSTR + 256)
                  * sizeof(float);
    static int attn_attr_set = 0;
    if (!attn_attr_set) {
        cudaFuncSetAttribute(attn_kernel,
                             cudaFuncAttributeMaxDynamicSharedMemorySize,
                             (int)smem);
        attn_attr_set = 1;
    }
    attn_kernel<<<dim3(Nn / 128, Bb), 256, smem>>>();

    wconv_kernel<<<dim3(Nn / 64, Dd / 128, Bb), 256>>>(Ww, Wb);
    zero_acc_kernel<<<1, 512>>>();
    stats_kernel<<<dim3(Dd, Bb), 256>>>();
    finalize_kernel<<<1, 256>>>();
    final_kernel<<<(size_t)(Bb * Dd * Nn) / (256 * 4), 256>>>(f, gma, bta, out);
}

// round 3
// speedup vs baseline: 4.2381x; 1.4582x over previous
#include <cuda_runtime.h>
#include <cuda_bf16.h>
#include <math.h>
#include <stdint.h>

#define Bb 2
#define Dd 256
#define Nn 8192
#define CIc 128
#define Mm 4096

// attention smem strides (32-bit units; all chosen conflict-free for frag reads)
#define THSTR 132 // theta [q][c] fp32
#define KSTR  72  // phi   [c][k] fp32
#define GSTR  72  // g / P bf16 halfword stride (72h = 36 words, 36 mod 32 = 4)
// proj/wconv smem strides
#define WS  36    // weight tile [row][k] fp32  (36 mod 32 = 4)
#define FS  136   // B tile [k][n] fp32         (136 mod 32 = 8)

// -------- scratch (static device globals; no runtime allocation) --------
__device__ float  d_theta[Bb*CIc*Nn];   // (B, CI, N)
__device__ float  d_gp[Bb*CIc*Mm];      // pooled g   (B, CI, M)
__device__ float  d_php[Bb*CIc*Mm];     // pooled phi (B, CI, M)
__device__ float  d_y[Bb*CIc*Nn];       // attention output (B, CI, N)
__device__ float  d_Wy[Bb*Dd*Nn];       // W conv output (B, D, N)
__device__ double d_acc[2*Dd];          // BN sum / sumsq accumulators
__device__ float  d_stats[2*Dd];        // per-channel mean, inv_std

// ---------------- helpers ----------------
__device__ __forceinline__ float tf32r(float x) {
    uint32_t u;
    asm("cvt.rna.tf32.f32 %0, %1;" : "=r"(u) : "f"(x));
    return __uint_as_float(u);
}

__device__ __forceinline__ void mma_tf32(float* d, const uint32_t* a,
                                         uint32_t b0, uint32_t b1) {
    asm volatile(
        "mma.sync.aligned.m16n8k8.row.col.f32.tf32.tf32.f32 "
        "{%0,%1,%2,%3},{%4,%5,%6,%7},{%8,%9},{%0,%1,%2,%3};"
        : "+f"(d[0]), "+f"(d[1]), "+f"(d[2]), "+f"(d[3])
        : "r"(a[0]), "r"(a[1]), "r"(a[2]), "r"(a[3]), "r"(b0), "r"(b1));
}

__device__ __forceinline__ void mma_bf16(float* d, const uint32_t* a,
                                         uint32_t b0, uint32_t b1) {
    asm volatile(
        "mma.sync.aligned.m16n8k16.row.col.f32.bf16.bf16.f32 "
        "{%0,%1,%2,%3},{%4,%5,%6,%7},{%8,%9},{%0,%1,%2,%3};"
        : "+f"(d[0]), "+f"(d[1]), "+f"(d[2]), "+f"(d[3])
        : "r"(a[0]), "r"(a[1]), "r"(a[2]), "r"(a[3]), "r"(b0), "r"(b1));
}

// ============================================================================
// Kernel 1: three 1x1-conv projections on tensor cores (tf32).
// CTA tile: 128 CI-rows x 128 n-cols, K = D = 256. grid (N/128, 3, B).
// Warp tile: 32c x 64n (warps 4x2). g & phi fused maxpool2 in epilogue.
// ============================================================================
__global__ __launch_bounds__(256) void proj_tc(
    const float* __restrict__ f,
    const float* __restrict__ gw, const float* __restrict__ gb,
    const float* __restrict__ tw, const float* __restrict__ tb,
    const float* __restrict__ pw, const float* __restrict__ pb)
{
    const int zi = blockIdx.y;
    const float* W  = (zi == 0) ? tw : (zi == 1) ? gw : pw;
    const float* bs = (zi == 0) ? tb : (zi == 1) ? gb : pb;
    float* out      = (zi == 0) ? d_theta : (zi == 1) ? d_gp : d_php;

    const int b    = blockIdx.z;
    const int n0   = blockIdx.x * 128;
    const int tid  = threadIdx.x;
    const int warp = tid >> 5;
    const int lane = tid & 31;
    const int grp  = lane >> 2;
    const int tig  = lane & 3;
    const int Cw   = (warp >> 1) * 32;
    const int Nw   = (warp & 1) * 64;

    __shared__ float w_sm[128 * WS];  // [c][d-chunk]
    __shared__ float f_sm[32 * FS];   // [d][n]
    const uint32_t* wu = (const uint32_t*)w_sm;
    const uint32_t* fu = (const uint32_t*)f_sm;

    float acc[2][8][4];
    #pragma unroll
    for (int mt = 0; mt < 2; mt++)
        #pragma unroll
        for (int nt = 0; nt < 8; nt++)
            #pragma unroll
            for (int r = 0; r < 4; r++) acc[mt][nt][r] = 0.f;

    const float* fb = f + (size_t)b * Dd * Nn;

    for (int d0 = 0; d0 < Dd; d0 += 32) {
        __syncthreads();
        #pragma unroll
        for (int r = 0; r < 2; r++) {     // W chunk: 128c x 32d
            int idx = (tid + r * 256) * 8;
            int c = idx >> 5, dl = idx & 31;
            float4 v0 = *(const float4*)&W[c * Dd + d0 + dl];
            float4 v1 = *(const float4*)&W[c * Dd + d0 + dl + 4];
            *(float4*)&w_sm[c * WS + dl] =
                make_float4(tf32r(v0.x), tf32r(v0.y), tf32r(v0.z), tf32r(v0.w));
            *(float4*)&w_sm[c * WS + dl + 4] =
                make_float4(tf32r(v1.x), tf32r(v1.y), tf32r(v1.z), tf32r(v1.w));
        }
        #pragma unroll
        for (int r = 0; r < 4; r++) {     // f chunk: 32d x 128n
            int idx = (tid + r * 256) * 4;
            int dd2 = idx >> 7, nn2 = idx & 127;
            float4 v = *(const float4*)&fb[(size_t)(d0 + dd2) * Nn + n0 + nn2];
            *(float4*)&f_sm[dd2 * FS + nn2] =
                make_float4(tf32r(v.x), tf32r(v.y), tf32r(v.z), tf32r(v.w));
        }
        __syncthreads();

        #pragma unroll
        for (int k8 = 0; k8 < 4; k8++) {
            const int col = k8 * 8 + tig;
            uint32_t A[2][4];
            #pragma unroll
            for (int mt = 0; mt < 2; mt++) {
                int rb = Cw + mt * 16 + grp;
                A[mt][0] = wu[(rb    ) * WS + col    ];
                A[mt][1] = wu[(rb + 8) * WS + col    ];
                A[mt][2] = wu[(rb    ) * WS + col + 4];
                A[mt][3] = wu[(rb + 8) * WS + col + 4];
            }
            #pragma unroll
            for (int nt = 0; nt < 8; nt++) {
                uint32_t b0 = fu[(col    ) * FS + Nw + nt * 8 + grp];
                uint32_t b1 = fu[(col + 4) * FS + Nw + nt * 8 + grp];
                mma_tf32(acc[0][nt], A[0], b0, b1);
                mma_tf32(acc[1][nt], A[1], b0, b1);
            }
        }
    }

    if (zi == 0) {
        #pragma unroll
        for (int mt = 0; mt < 2; mt++) {
            int c  = Cw + mt * 16 + grp;
            float bias0 = bs[c], bias1 = bs[c + 8];
            #pragma unroll
            for (int nt = 0; nt < 8; nt++) {
                int n = n0 + Nw + nt * 8 + 2 * tig;
                *(float2*)&out[((size_t)b * CIc + c) * Nn + n] =
                    make_float2(acc[mt][nt][0] + bias0, acc[mt][nt][1] + bias0);
                *(float2*)&out[((size_t)b * CIc + c + 8) * Nn + n] =
                    make_float2(acc[mt][nt][2] + bias1, acc[mt][nt][3] + bias1);
            }
        }
    } else {
        #pragma unroll
        for (int mt = 0; mt < 2; mt++) {
            int c  = Cw + mt * 16 + grp;
            float bias0 = bs[c], bias1 = bs[c + 8];
            #pragma unroll
            for (int nt = 0; nt < 8; nt++) {
                int m = (n0 + Nw) / 2 + nt * 4 + tig;
                out[((size_t)b * CIc + c) * Mm + m] =
                    fmaxf(acc[mt][nt][0], acc[mt][nt][1]) + bias0;
                out[((size_t)b * CIc + c + 8) * Mm + m] =
                    fmaxf(acc[mt][nt][2], acc[mt][nt][3]) + bias1;
            }
        }
    }
}

// ============================================================================
// Kernel 2: tensor-core attention.
// GEMM1 (logits): tf32 m16n8k8, theta A-fragments half register-cached.
// GEMM2 (P.g^T):  bf16 m16n8k16, P and g stored bf16 in smem.
// CTA: 128 queries x 4096 keys in 64-key chunks; 8 warps.
// ============================================================================
__global__ __launch_bounds__(256, 1) void attn_kernel()
{
    extern __shared__ float sm[];
    float* th = sm;                               // [128 q][THSTR] fp32
    float* ph = th + 128 * THSTR;                 // [128 c][KSTR]  fp32
    __nv_bfloat16* gg = (__nv_bfloat16*)(ph + 128 * KSTR);  // [128 c][GSTR]
    __nv_bfloat16* Pm = gg + 128 * GSTR;          // [128 q][GSTR]
    float* l2 = (float*)(Pm + 128 * GSTR);        // [2][128]

    const uint32_t* thu = (const uint32_t*)th;
    const uint32_t* phu = (const uint32_t*)ph;

    const int b    = blockIdx.y;
    const int q0g  = blockIdx.x * 128;
    const int tid  = threadIdx.x;
    const int warp = tid >> 5;
    const int lane = tid & 31;
    const int grp  = lane >> 2;
    const int tig  = lane & 3;

    const int wq1 = warp & 3, wk1 = warp >> 2;
    const int Q1 = wq1 * 32, K1 = wk1 * 32;
    const int Q2 = (warp & 3) * 32, C2 = (warp >> 2) * 64;

    const float* theta = d_theta + (size_t)b * CIc * Nn;
    const float* phi   = d_php   + (size_t)b * CIc * Mm;
    const float* g     = d_gp    + (size_t)b * CIc * Mm;

    // prologue: theta tile 128c x 128q, transposed to [q][c], tf32-rounded
    #pragma unroll
    for (int r = 0; r < 16; r++) {
        int idx = (tid + r * 256) * 4;
        int c = idx >> 7, q = idx & 127;
        float4 v = *(const float4*)&theta[(size_t)c * Nn + q0g + q];
        th[(q + 0) * THSTR + c] = tf32r(v.x);
        th[(q + 1) * THSTR + c] = tf32r(v.y);
        th[(q + 2) * THSTR + c] = tf32r(v.z);
        th[(q + 3) * THSTR + c] = tf32r(v.w);
    }
    l2[tid] = 0.f;
    __syncthreads();

    // register-cache A fragments for c8 = 0..7 (theta is loop-invariant)
    uint32_t Ac[8][2][4];
    #pragma unroll
    for (int c8 = 0; c8 < 8; c8++) {
        const int col = c8 * 8 + tig;
        #pragma unroll
        for (int mt = 0; mt < 2; mt++) {
            int rb = Q1 + mt * 16 + grp;
            Ac[c8][mt][0] = thu[(rb    ) * THSTR + col    ];
            Ac[c8][mt][1] = thu[(rb + 8) * THSTR + col    ];
            Ac[c8][mt][2] = thu[(rb    ) * THSTR + col + 4];
            Ac[c8][mt][3] = thu[(rb + 8) * THSTR + col + 4];
        }
    }

    float yacc[2][8][4];
    #pragma unroll
    for (int mt = 0; mt < 2; mt++)
        #pragma unroll
        for (int nt = 0; nt < 8; nt++)
            #pragma unroll
            for (int r = 0; r < 4; r++) yacc[mt][nt][r] = 0.f;

    for (int k0 = 0; k0 < Mm; k0 += 64) {
        __syncthreads();   // prev GEMM2 done reading ph/gg/Pm

        #pragma unroll
        for (int r = 0; r < 8; r++) {   // phi (tf32) & g (bf16) tiles 128c x 64k
            int idx = (tid + r * 256) * 4;
            int c = idx >> 6, k = idx & 63;
            float4 v = *(const float4*)&phi[(size_t)c * Mm + k0 + k];
            ph[c * KSTR + k + 0] = tf32r(v.x);
            ph[c * KSTR + k + 1] = tf32r(v.y);
            ph[c * KSTR + k + 2] = tf32r(v.z);
            ph[c * KSTR + k + 3] = tf32r(v.w);
            float4 u = *(const float4*)&g[(size_t)c * Mm + k0 + k];
            __nv_bfloat162 g0, g1;
            g0.x = __float2bfloat16_rn(u.x); g0.y = __float2bfloat16_rn(u.y);
            g1.x = __float2bfloat16_rn(u.z); g1.y = __float2bfloat16_rn(u.w);
            *(__nv_bfloat162*)&gg[c * GSTR + k    ] = g0;
            *(__nv_bfloat162*)&gg[c * GSTR + k + 2] = g1;
        }
        __syncthreads();

        // ---- GEMM1: S[32q x 32k] = theta^T . phi over CI=128 (tf32) ----
        float s[2][4][4];
        #pragma unroll
        for (int mt = 0; mt < 2; mt++)
            #pragma unroll
            for (int nt = 0; nt < 4; nt++)
                #pragma unroll
                for (int r = 0; r < 4; r++) s[mt][nt][r] = 0.f;

        #pragma unroll
        for (int c8 = 0; c8 < 16; c8++) {
            const int col = c8 * 8 + tig;
            uint32_t A[2][4];
            if (c8 < 8) {
                #pragma unroll
                for (int mt = 0; mt < 2; mt++)
                    #pragma unroll
                    for (int r = 0; r < 4; r++) A[mt][r] = Ac[c8][mt][r];
            } else {
                #pragma unroll
                for (int mt = 0; mt < 2; mt++) {
                    int rb = Q1 + mt * 16 + grp;
                    A[mt][0] = thu[(rb    ) * THSTR + col    ];
                    A[mt][1] = thu[(rb + 8) * THSTR + col    ];
                    A[mt][2] = thu[(rb    ) * THSTR + col + 4];
                    A[mt][3] = thu[(rb + 8) * THSTR + col + 4];
                }
            }
            #pragma unroll
            for (int nt = 0; nt < 4; nt++) {
                uint32_t b0 = phu[(col    ) * KSTR + K1 + nt * 8 + grp];
                uint32_t b1 = phu[(col + 4) * KSTR + K1 + nt * 8 + grp];
                mma_tf32(s[0][nt], A[0], b0, b1);
                mma_tf32(s[1][nt], A[1], b0, b1);
            }
        }

        // ---- exp -> Pm (bf16), accumulate row sums (of bf16 values) ----
        #pragma unroll
        for (int mt = 0; mt < 2; mt++) {
            #pragma unroll
            for (int h = 0; h < 2; h++) {
                int q = Q1 + mt * 16 + grp + 8 * h;
                float lp = 0.f;
                #pragma unroll
                for (int nt = 0; nt < 4; nt++) {
                    float w0 = __expf(s[mt][nt][2 * h    ]);
                    float w1 = __expf(s[mt][nt][2 * h + 1]);
                    __nv_bfloat162 pk;
                    pk.x = __float2bfloat16_rn(w0);
                    pk.y = __float2bfloat16_rn(w1);
                    *(__nv_bfloat162*)&Pm[q * GSTR + K1 + nt * 8 + 2 * tig] = pk;
                    lp += __bfloat162float(pk.x) + __bfloat162float(pk.y);
                }
                lp += __shfl_xor_sync(0xffffffffu, lp, 1);
                lp += __shfl_xor_sync(0xffffffffu, lp, 2);
                if (tig == 0) l2[wk1 * 128 + q] += lp;
            }
        }
        __syncthreads();

        // ---- GEMM2: Y[32q x 64c] += P[32q x 64k] . g^T (bf16 m16n8k16) ----
        #pragma unroll
        for (int kk = 0; kk < 4; kk++) {
            uint32_t A[2][4];
            #pragma unroll
            for (int mt = 0; mt < 2; mt++) {
                int rb = Q2 + mt * 16 + grp;
                const int ko = kk * 16 + 2 * tig;
                A[mt][0] = *(const uint32_t*)&Pm[(rb    ) * GSTR + ko    ];
                A[mt][1] = *(const uint32_t*)&Pm[(rb + 8) * GSTR + ko    ];
                A[mt][2] = *(const uint32_t*)&Pm[(rb    ) * GSTR + ko + 8];
                A[mt][3] = *(const uint32_t*)&Pm[(rb + 8) * GSTR + ko + 8];
            }
            #pragma unroll
            for (int nt = 0; nt < 8; nt++) {
                const int crow = C2 + nt * 8 + grp;
                const int ko = kk * 16 + 2 * tig;
                uint32_t b0 = *(const uint32_t*)&gg[crow * GSTR + ko    ];
                uint32_t b1 = *(const uint32_t*)&gg[crow * GSTR + ko + 8];
                mma_bf16(yacc[0][nt], A[0], b0, b1);
                mma_bf16(yacc[1][nt], A[1], b0, b1);
            }
        }
    }

    __syncthreads();
    if (tid < 128) l2[tid] = 1.f / (l2[tid] + l2[128 + tid]);
    __syncthreads();

    float* yb = d_y + (size_t)b * CIc * Nn;
    #pragma unroll
    for (int mt = 0; mt < 2; mt++) {
        int q_lo = Q2 + mt * 16 + grp;
        int q_hi = q_lo + 8;
        float ilo = l2[q_lo], ihi = l2[q_hi];
        #pragma unroll
        for (int nt = 0; nt < 8; nt++) {
            int c0 = C2 + nt * 8 + 2 * tig;
            yb[(size_t)(c0    ) * Nn + q0g + q_lo] = yacc[mt][nt][0] * ilo;
            yb[(size_t)(c0 + 1) * Nn + q0g + q_lo] = yacc[mt][nt][1] * ilo;
            yb[(size_t)(c0    ) * Nn + q0g + q_hi] = yacc[mt][nt][2] * ihi;
            yb[(size_t)(c0 + 1) * Nn + q0g + q_hi] = yacc[mt][nt][3] * ihi;
        }
    }
}

// ============================================================================
// Kernel 3: W 1x1 conv on tensor cores (tf32). Wy = Ww(256x128) @ y + Wb.
// CTA tile: 128d x 128n, K = CI = 128. grid (N/128, D/128, B).
// ============================================================================
__global__ __launch_bounds__(256) void wconv_tc(
    const float* __restrict__ Ww, const float* __restrict__ Wb)
{
    const int b    = blockIdx.z;
    const int dblk = blockIdx.y * 128;
    const int n0   = blockIdx.x * 128;
    const int tid  = threadIdx.x;
    const int warp = tid >> 5;
    const int lane = tid & 31;
    const int grp  = lane >> 2;
    const int tig  = lane & 3;
    const int Dw   = (warp >> 1) * 32;
    const int Nw   = (warp & 1) * 64;

    __shared__ float w_sm[128 * WS];  // [d][c-chunk]
    __shared__ float y_sm[32 * FS];   // [c][n]
    const uint32_t* wu = (const uint32_t*)w_sm;
    const uint32_t* yu = (const uint32_t*)y_sm;

    float acc[2][8][4];
    #pragma unroll
    for (int mt = 0; mt < 2; mt++)
        #pragma unroll
        for (int nt = 0; nt < 8; nt++)
            #pragma unroll
            for (int r = 0; r < 4; r++) acc[mt][nt][r] = 0.f;

    const float* yb = d_y + (size_t)b * CIc * Nn;

    for (int c0 = 0; c0 < CIc; c0 += 32) {
        __syncthreads();
        #pragma unroll
        for (int r = 0; r < 2; r++) {     // Ww chunk: 128d x 32c
            int idx = (tid + r * 256) * 8;
            int dl = idx >> 5, cl = idx & 31;
            float4 v0 = *(const float4*)&Ww[(size_t)(dblk + dl) * CIc + c0 + cl];
            float4 v1 = *(const float4*)&Ww[(size_t)(dblk + dl) * CIc + c0 + cl + 4];
            *(float4*)&w_sm[dl * WS + cl] =
                make_float4(tf32r(v0.x), tf32r(v0.y), tf32r(v0.z), tf32r(v0.w));
            *(float4*)&w_sm[dl * WS + cl + 4] =
                make_float4(tf32r(v1.x), tf32r(v1.y), tf32r(v1.z), tf32r(v1.w));
        }
        #pragma unroll
        for (int r = 0; r < 4; r++) {     // y chunk: 32c x 128n
            int idx = (tid + r * 256) * 4;
            int cc = idx >> 7, nn2 = idx & 127;
            float4 v = *(const float4*)&yb[(size_t)(c0 + cc) * Nn + n0 + nn2];
            *(float4*)&y_sm[cc * FS + nn2] =
                make_float4(tf32r(v.x), tf32r(v.y), tf32r(v.z), tf32r(v.w));
        }
        __syncthreads();

        #pragma unroll
        for (int k8 = 0; k8 < 4; k8++) {
            const int col = k8 * 8 + tig;
            uint32_t A[2][4];
            #pragma unroll
            for (int mt = 0; mt < 2; mt++) {
                int rb = Dw + mt * 16 + grp;
                A[mt][0] = wu[(rb    ) * WS + col    ];
                A[mt][1] = wu[(rb + 8) * WS + col    ];
                A[mt][2] = wu[(rb    ) * WS + col + 4];
                A[mt][3] = wu[(rb + 8) * WS + col + 4];
            }
            #pragma unroll
            for (int nt = 0; nt < 8; nt++) {
                uint32_t b0 = yu[(col    ) * FS + Nw + nt * 8 + grp];
                uint32_t b1 = yu[(col + 4) * FS + Nw + nt * 8 + grp];
                mma_tf32(acc[0][nt], A[0], b0, b1);
                mma_tf32(acc[1][nt], A[1], b0, b1);
            }
        }
    }

    #pragma unroll
    for (int mt = 0; mt < 2; mt++) {
        int d = dblk + Dw + mt * 16 + grp;
        float bias0 = Wb[d], bias1 = Wb[d + 8];
        #pragma unroll
        for (int nt = 0; nt < 8; nt++) {
            int n = n0 + Nw + nt * 8 + 2 * tig;
            *(float2*)&d_Wy[((size_t)b * Dd + d) * Nn + n] =
                make_float2(acc[mt][nt][0] + bias0, acc[mt][nt][1] + bias0);
            *(float2*)&d_Wy[((size_t)b * Dd + d + 8) * Nn + n] =
                make_float2(acc[mt][nt][2] + bias1, acc[mt][nt][3] + bias1);
        }
    }
}

// ============================================================================
// Kernel 4a/4b/4c: BN stats — zero, accumulate, finalize
// ============================================================================
__global__ void zero_acc_kernel()
{
    if (threadIdx.x < 2 * Dd) d_acc[threadIdx.x] = 0.0;
}

__global__ __launch_bounds__(256) void stats_kernel()
{
    __shared__ double sh[256], sh2[256];
    const int d = blockIdx.x, b = blockIdx.y, tid = threadIdx.x;
    const float4* p = (const float4*)(d_Wy + ((size_t)b * Dd + d) * Nn);
    double s = 0.0, ss = 0.0;
    #pragma unroll
    for (int r = 0; r < 8; r++) {
        float4 v = p[tid + r * 256];
        s  += (double)v.x + (double)v.y + (double)v.z + (double)v.w;
        ss += (double)v.x * v.x + (double)v.y * v.y
            + (double)v.z * v.z + (double)v.w * v.w;
    }
    sh[tid] = s; sh2[tid] = ss;
    __syncthreads();
    for (int o = 128; o > 0; o >>= 1) {
        if (tid < o) { sh[tid] += sh[tid + o]; sh2[tid] += sh2[tid + o]; }
        __syncthreads();
    }
    if (tid == 0) {
        atomicAdd(&d_acc[d],      sh[0]);
        atomicAdd(&d_acc[Dd + d], sh2[0]);
    }
}

__global__ void finalize_kernel()
{
    int d = threadIdx.x;
    if (d < Dd) {
        double cnt  = (double)(Bb * Nn);
        double mean = d_acc[d] / cnt;
        double var  = d_acc[Dd + d] / cnt - mean * mean;
        d_stats[d]      = (float)mean;
        d_stats[Dd + d] = (float)(1.0 / sqrt(var + 1e-5));
    }
}

// ============================================================================
// Kernel 5: normalize + affine + residual
// ============================================================================
__global__ __launch_bounds__(256) void final_kernel(
    const float* __restrict__ f, const float* __restrict__ gamma,
    const float* __restrict__ beta, float* __restrict__ out)
{
    size_t i4 = (size_t)blockIdx.x * 256 + threadIdx.x;
    size_t i  = i4 * 4;
    int d = (int)((i / Nn) % Dd);
    float mean = d_stats[d];
    float inv  = d_stats[Dd + d];
    float gm = gamma[d] * inv;
    float bt = beta[d] - mean * gm;
    float4 w  = *(const float4*)&d_Wy[i];
    float4 fv = *(const float4*)&f[i];
    float4 o;
    o.x = fmaf(w.x, gm, bt) + fv.x;
    o.y = fmaf(w.y, gm, bt) + fv.y;
    o.z = fmaf(w.z, gm, bt) + fv.z;
    o.w = fmaf(w.w, gm, bt) + fv.w;
    *(float4*)&out[i] = o;
}

// ============================================================================
extern "C" void kernel_launch(void* const* d_in, const int* in_sizes, int n_in,
                              void* d_out, int out_size)
{
    const float* f   = (const float*)d_in[0];
    const float* gw  = (const float*)d_in[1];
    const float* gb  = (const float*)d_in[2];
    const float* tw  = (const float*)d_in[3];
    const float* tb  = (const float*)d_in[4];
    const float* pw  = (const float*)d_in[5];
    const float* pb  = (const float*)d_in[6];
    const float* Ww  = (const float*)d_in[7];
    const float* Wb  = (const float*)d_in[8];
    const float* gma = (const float*)d_in[9];
    const float* bta = (const float*)d_in[10];
    float* out = (float*)d_out;

    proj_tc<<<dim3(Nn / 128, 3, Bb), 256>>>(f, gw, gb, tw, tb, pw, pb);

    size_t smem = (size_t)(128 * THSTR + 128 * KSTR) * 4
                + (size_t)(2 * 128 * GSTR) * 2 + 256 * 4;
    static int attn_attr_set = 0;
    if (!attn_attr_set) {
        cudaFuncSetAttribute(attn_kernel,
                             cudaFuncAttributeMaxDynamicSharedMemorySize,
                             (int)smem);
        attn_attr_set = 1;
    }
    attn_kernel<<<dim3(Nn / 128, Bb), 256, smem>>>();

    wconv_tc<<<dim3(Nn / 128, Dd / 128, Bb), 256>>>(Ww, Wb);
    zero_acc_kernel<<<1, 512>>>();
    stats_kernel<<<dim3(Dd, Bb), 256>>>();
    finalize_kernel<<<1, 256>>>();
    final_kernel<<<(size_t)(Bb * Dd * Nn) / (256 * 4), 256>>>(f, gma, bta, out);
}

// round 4
// speedup vs baseline: 5.6714x; 1.3382x over previous
#include <cuda_runtime.h>
#include <cuda_bf16.h>
#include <cuda_fp16.h>
#include <math.h>
#include <stdint.h>

#define Bb 2
#define Dd 256
#define Nn 8192
#define CIc 128
#define Mm 4096

// proj/wconv smem strides (fp32 words)
#define WS  36
#define FS  136
// attention strides in halfwords
#define THH 136   // theta [q][c] fp16   (68 words: 68 mod 32 = 4 -> conflict-free)
#define PHH 136   // phi   [k][c] fp16
#define GH  72    // g     [c][k] bf16   (36 words: 4grp+tig distinct)
#define PMH 72    // P     [q][k] bf16

// -------- scratch (static device globals; no runtime allocation) --------
__device__ float          d_theta[Bb*CIc*Nn];  // (B, CI, N) fp32
__device__ __half         d_phT[Bb*Mm*CIc];    // pooled phi, (B, M, CI) fp16
__device__ __nv_bfloat16  d_gbf[Bb*CIc*Mm];    // pooled g,   (B, CI, M) bf16
__device__ float          d_y[Bb*CIc*Nn];      // attention output (B, CI, N)
__device__ float          d_Wy[Bb*Dd*Nn];      // W conv output (B, D, N)
__device__ double         d_acc[4*Dd];         // BN partial sums per (b, d)
__device__ float          d_stats[2*Dd];       // per-channel mean, inv_std

// ---------------- helpers ----------------
__device__ __forceinline__ float tf32r(float x) {
    uint32_t u;
    asm("cvt.rna.tf32.f32 %0, %1;" : "=r"(u) : "f"(x));
    return __uint_as_float(u);
}

__device__ __forceinline__ void mma_tf32(float* d, const uint32_t* a,
                                         uint32_t b0, uint32_t b1) {
    asm volatile(
        "mma.sync.aligned.m16n8k8.row.col.f32.tf32.tf32.f32 "
        "{%0,%1,%2,%3},{%4,%5,%6,%7},{%8,%9},{%0,%1,%2,%3};"
        : "+f"(d[0]), "+f"(d[1]), "+f"(d[2]), "+f"(d[3])
        : "r"(a[0]), "r"(a[1]), "r"(a[2]), "r"(a[3]), "r"(b0), "r"(b1));
}

__device__ __forceinline__ void mma_f16(float* d, const uint32_t* a,
                                        uint32_t b0, uint32_t b1) {
    asm volatile(
        "mma.sync.aligned.m16n8k16.row.col.f32.f16.f16.f32 "
        "{%0,%1,%2,%3},{%4,%5,%6,%7},{%8,%9},{%0,%1,%2,%3};"
        : "+f"(d[0]), "+f"(d[1]), "+f"(d[2]), "+f"(d[3])
        : "r"(a[0]), "r"(a[1]), "r"(a[2]), "r"(a[3]), "r"(b0), "r"(b1));
}

__device__ __forceinline__ void mma_bf16(float* d, const uint32_t* a,
                                         uint32_t b0, uint32_t b1) {
    asm volatile(
        "mma.sync.aligned.m16n8k16.row.col.f32.bf16.bf16.f32 "
        "{%0,%1,%2,%3},{%4,%5,%6,%7},{%8,%9},{%0,%1,%2,%3};"
        : "+f"(d[0]), "+f"(d[1]), "+f"(d[2]), "+f"(d[3])
        : "r"(a[0]), "r"(a[1]), "r"(a[2]), "r"(a[3]), "r"(b0), "r"(b1));
}

__device__ __forceinline__ void cp16(uint32_t dst, const void* src) {
    asm volatile("cp.async.cg.shared.global [%0], [%1], 16;\n"
                 :: "r"(dst), "l"(src));
}

// ============================================================================
// Kernel 1: three 1x1-conv projections on tensor cores (tf32).
// theta -> fp32 (B,CI,N); g -> bf16 (B,CI,M) pooled; phi -> fp16 (B,M,CI) pooled.
// ============================================================================
__global__ __launch_bounds__(256) void proj_tc(
    const float* __restrict__ f,
    const float* __restrict__ gw, const float* __restrict__ gb,
    const float* __restrict__ tw, const float* __restrict__ tb,
    const float* __restrict__ pw, const float* __restrict__ pb)
{
    const int zi = blockIdx.y;
    const float* W  = (zi == 0) ? tw : (zi == 1) ? gw : pw;
    const float* bs = (zi == 0) ? tb : (zi == 1) ? gb : pb;

    const int b    = blockIdx.z;
    const int n0   = blockIdx.x * 128;
    const int tid  = threadIdx.x;
    const int warp = tid >> 5;
    const int lane = tid & 31;
    const int grp  = lane >> 2;
    const int tig  = lane & 3;
    const int Cw   = (warp >> 1) * 32;
    const int Nw   = (warp & 1) * 64;

    __shared__ float w_sm[128 * WS];
    __shared__ float f_sm[32 * FS];
    const uint32_t* wu = (const uint32_t*)w_sm;
    const uint32_t* fu = (const uint32_t*)f_sm;

    float acc[2][8][4];
    #pragma unroll
    for (int mt = 0; mt < 2; mt++)
        #pragma unroll
        for (int nt = 0; nt < 8; nt++)
            #pragma unroll
            for (int r = 0; r < 4; r++) acc[mt][nt][r] = 0.f;

    const float* fb = f + (size_t)b * Dd * Nn;

    for (int d0 = 0; d0 < Dd; d0 += 32) {
        __syncthreads();
        #pragma unroll
        for (int r = 0; r < 2; r++) {
            int idx = (tid + r * 256) * 8;
            int c = idx >> 5, dl = idx & 31;
            float4 v0 = *(const float4*)&W[c * Dd + d0 + dl];
            float4 v1 = *(const float4*)&W[c * Dd + d0 + dl + 4];
            *(float4*)&w_sm[c * WS + dl] =
                make_float4(tf32r(v0.x), tf32r(v0.y), tf32r(v0.z), tf32r(v0.w));
            *(float4*)&w_sm[c * WS + dl + 4] =
                make_float4(tf32r(v1.x), tf32r(v1.y), tf32r(v1.z), tf32r(v1.w));
        }
        #pragma unroll
        for (int r = 0; r < 4; r++) {
            int idx = (tid + r * 256) * 4;
            int dd2 = idx >> 7, nn2 = idx & 127;
            float4 v = *(const float4*)&fb[(size_t)(d0 + dd2) * Nn + n0 + nn2];
            *(float4*)&f_sm[dd2 * FS + nn2] =
                make_float4(tf32r(v.x), tf32r(v.y), tf32r(v.z), tf32r(v.w));
        }
        __syncthreads();

        #pragma unroll
        for (int k8 = 0; k8 < 4; k8++) {
            const int col = k8 * 8 + tig;
            uint32_t A[2][4];
            #pragma unroll
            for (int mt = 0; mt < 2; mt++) {
                int rb = Cw + mt * 16 + grp;
                A[mt][0] = wu[(rb    ) * WS + col    ];
                A[mt][1] = wu[(rb + 8) * WS + col    ];
                A[mt][2] = wu[(rb    ) * WS + col + 4];
                A[mt][3] = wu[(rb + 8) * WS + col + 4];
            }
            #pragma unroll
            for (int nt = 0; nt < 8; nt++) {
                uint32_t b0 = fu[(col    ) * FS + Nw + nt * 8 + grp];
                uint32_t b1 = fu[(col + 4) * FS + Nw + nt * 8 + grp];
                mma_tf32(acc[0][nt], A[0], b0, b1);
                mma_tf32(acc[1][nt], A[1], b0, b1);
            }
        }
    }

    if (zi == 0) {          // theta: fp32 (B, CI, N)
        #pragma unroll
        for (int mt = 0; mt < 2; mt++) {
            int c = Cw + mt * 16 + grp;
            float bias0 = bs[c], bias1 = bs[c + 8];
            #pragma unroll
            for (int nt = 0; nt < 8; nt++) {
                int n = n0 + Nw + nt * 8 + 2 * tig;
                *(float2*)&d_theta[((size_t)b * CIc + c) * Nn + n] =
                    make_float2(acc[mt][nt][0] + bias0, acc[mt][nt][1] + bias0);
                *(float2*)&d_theta[((size_t)b * CIc + c + 8) * Nn + n] =
                    make_float2(acc[mt][nt][2] + bias1, acc[mt][nt][3] + bias1);
            }
        }
    } else if (zi == 1) {   // g: maxpool2 -> bf16 (B, CI, M)
        #pragma unroll
        for (int mt = 0; mt < 2; mt++) {
            int c = Cw + mt * 16 + grp;
            float bias0 = bs[c], bias1 = bs[c + 8];
            #pragma unroll
            for (int nt = 0; nt < 8; nt++) {
                int m = (n0 + Nw) / 2 + nt * 4 + tig;
                d_gbf[((size_t)b * CIc + c) * Mm + m] =
                    __float2bfloat16_rn(fmaxf(acc[mt][nt][0], acc[mt][nt][1]) + bias0);
                d_gbf[((size_t)b * CIc + c + 8) * Mm + m] =
                    __float2bfloat16_rn(fmaxf(acc[mt][nt][2], acc[mt][nt][3]) + bias1);
            }
        }
    } else {                // phi: maxpool2 -> fp16 (B, M, CI)
        #pragma unroll
        for (int mt = 0; mt < 2; mt++) {
            int c = Cw + mt * 16 + grp;
            float bias0 = bs[c], bias1 = bs[c + 8];
            #pragma unroll
            for (int nt = 0; nt < 8; nt++) {
                int m = (n0 + Nw) / 2 + nt * 4 + tig;
                d_phT[((size_t)b * Mm + m) * CIc + c] =
                    __float2half_rn(fmaxf(acc[mt][nt][0], acc[mt][nt][1]) + bias0);
                d_phT[((size_t)b * Mm + m) * CIc + c + 8] =
                    __float2half_rn(fmaxf(acc[mt][nt][2], acc[mt][nt][3]) + bias1);
            }
        }
    }
}

// ============================================================================
// Kernel 2: tensor-core attention, cp.async double-buffered.
// GEMM1: fp16 m16n8k16 (theta A-frags fully register-cached, 64 regs)
// GEMM2: bf16 m16n8k16
// ============================================================================
// smem layout (bytes)
#define SM_TH 0
#define SM_PH (128 * THH * 2)                    // 34816
#define SM_GG (SM_PH + 2 * 64 * PHH * 2)         // 69632
#define SM_PM (SM_GG + 2 * 128 * GH * 2)         // 106496
#define SM_L2 (SM_PM + 128 * PMH * 2)            // 124928
#define SM_TOTAL (SM_L2 + 256 * 4)               // 125952

__global__ __launch_bounds__(256, 1) void attn_kernel()
{
    extern __shared__ char smc[];
    __half*        th = (__half*)(smc + SM_TH);          // [128 q][THH]
    __half*        ph = (__half*)(smc + SM_PH);          // [2][64 k][PHH]
    __nv_bfloat16* gg = (__nv_bfloat16*)(smc + SM_GG);   // [2][128 c][GH]
    __nv_bfloat16* Pm = (__nv_bfloat16*)(smc + SM_PM);   // [128 q][PMH]
    float*         l2 = (float*)(smc + SM_L2);           // [2][128]
    const uint32_t smbase = (uint32_t)__cvta_generic_to_shared(smc);

    const int b    = blockIdx.y;
    const int q0g  = blockIdx.x * 128;
    const int tid  = threadIdx.x;
    const int warp = tid >> 5;
    const int lane = tid & 31;
    const int grp  = lane >> 2;
    const int tig  = lane & 3;

    const int wq1 = warp & 3, wk1 = warp >> 2;
    const int Q1 = wq1 * 32, K1 = wk1 * 32;
    const int Q2 = (warp & 3) * 32, C2 = (warp >> 2) * 64;

    const float*         theta = d_theta + (size_t)b * CIc * Nn;
    const __half*        phg   = d_phT   + (size_t)b * Mm * CIc;
    const __nv_bfloat16* ggm   = d_gbf   + (size_t)b * CIc * Mm;

    // ---- issue prefetch of chunk 0 (overlaps theta prologue) ----
    {
        #pragma unroll
        for (int r = 0; r < 4; r++) {
            int gI = tid + r * 256;               // 0..1023
            int k = gI >> 4, off = (gI & 15) * 8; // phi: 16 granules per 256B row
            cp16(smbase + SM_PH + (k * PHH + off) * 2, phg + (size_t)k * CIc + off);
            int c = gI >> 3, o2 = (gI & 7) * 8;   // g: 8 granules per 128B row
            cp16(smbase + SM_GG + (c * GH + o2) * 2, ggm + (size_t)c * Mm + o2);
        }
        asm volatile("cp.async.commit_group;");
    }

    // ---- theta prologue: transpose to [q][c] fp16 ----
    #pragma unroll
    for (int r = 0; r < 16; r++) {
        int idx = (tid + r * 256) * 4;
        int c = idx >> 7, q = idx & 127;
        float4 v = *(const float4*)&theta[(size_t)c * Nn + q0g + q];
        th[(q + 0) * THH + c] = __float2half_rn(v.x);
        th[(q + 1) * THH + c] = __float2half_rn(v.y);
        th[(q + 2) * THH + c] = __float2half_rn(v.z);
        th[(q + 3) * THH + c] = __float2half_rn(v.w);
    }
    l2[tid] = 0.f;
    __syncthreads();

    // ---- cache ALL theta A-fragments (8 k16 steps x 2 mt x 4 regs) ----
    uint32_t Ac[8][2][4];
    #pragma unroll
    for (int c8 = 0; c8 < 8; c8++) {
        const int co = c8 * 16 + 2 * tig;
        #pragma unroll
        for (int mt = 0; mt < 2; mt++) {
            int rb = Q1 + mt * 16 + grp;
            Ac[c8][mt][0] = *(const uint32_t*)&th[(rb    ) * THH + co    ];
            Ac[c8][mt][1] = *(const uint32_t*)&th[(rb + 8) * THH + co    ];
            Ac[c8][mt][2] = *(const uint32_t*)&th[(rb    ) * THH + co + 8];
            Ac[c8][mt][3] = *(const uint32_t*)&th[(rb + 8) * THH + co + 8];
        }
    }

    float yacc[2][8][4];
    #pragma unroll
    for (int mt = 0; mt < 2; mt++)
        #pragma unroll
        for (int nt = 0; nt < 8; nt++)
            #pragma unroll
            for (int r = 0; r < 4; r++) yacc[mt][nt][r] = 0.f;

    for (int ic = 0; ic < Mm / 64; ic++) {
        const int buf = ic & 1;
        const __half*        phb = ph + buf * 64 * PHH;
        const __nv_bfloat16* ggb = gg + buf * 128 * GH;

        asm volatile("cp.async.wait_group 0;");
        __syncthreads();   // loads visible to all; all warps done with buf^1

        if (ic + 1 < Mm / 64) {   // prefetch next chunk into the other buffer
            const int k0n = (ic + 1) * 64;
            const uint32_t phd = smbase + SM_PH + (buf ^ 1) * 64 * PHH * 2;
            const uint32_t ggd = smbase + SM_GG + (buf ^ 1) * 128 * GH * 2;
            const __half*        phs = phg + (size_t)k0n * CIc;
            const __nv_bfloat16* ggs = ggm + k0n;
            #pragma unroll
            for (int r = 0; r < 4; r++) {
                int gI = tid + r * 256;
                int k = gI >> 4, off = (gI & 15) * 8;
                cp16(phd + (k * PHH + off) * 2, phs + (size_t)k * CIc + off);
                int c = gI >> 3, o2 = (gI & 7) * 8;
                cp16(ggd + (c * GH + o2) * 2, ggs + (size_t)c * Mm + o2);
            }
            asm volatile("cp.async.commit_group;");
        }

        // ---- GEMM1: S[32q x 32k] = theta . phi^T  (fp16, K=128) ----
        float s[2][4][4];
        #pragma unroll
        for (int mt = 0; mt < 2; mt++)
            #pragma unroll
            for (int nt = 0; nt < 4; nt++)
                #pragma unroll
                for (int r = 0; r < 4; r++) s[mt][nt][r] = 0.f;

        #pragma unroll
        for (int c8 = 0; c8 < 8; c8++) {
            const int co = c8 * 16 + 2 * tig;
            #pragma unroll
            for (int nt = 0; nt < 4; nt++) {
                const __half* row = phb + (K1 + nt * 8 + grp) * PHH;
                uint32_t b0 = *(const uint32_t*)&row[co    ];
                uint32_t b1 = *(const uint32_t*)&row[co + 8];
                mma_f16(s[0][nt], Ac[c8][0], b0, b1);
                mma_f16(s[1][nt], Ac[c8][1], b0, b1);
            }
        }

        // ---- exp -> Pm (bf16), accumulate row sums of the bf16 values ----
        #pragma unroll
        for (int mt = 0; mt < 2; mt++) {
            #pragma unroll
            for (int h = 0; h < 2; h++) {
                int q = Q1 + mt * 16 + grp + 8 * h;
                float lp = 0.f;
                #pragma unroll
                for (int nt = 0; nt < 4; nt++) {
                    float w0 = __expf(s[mt][nt][2 * h    ]);
                    float w1 = __expf(s[mt][nt][2 * h + 1]);
                    __nv_bfloat162 pk;
                    pk.x = __float2bfloat16_rn(w0);
                    pk.y = __float2bfloat16_rn(w1);
                    *(__nv_bfloat162*)&Pm[q * PMH + K1 + nt * 8 + 2 * tig] = pk;
                    lp += __bfloat162float(pk.x) + __bfloat162float(pk.y);
                }
                lp += __shfl_xor_sync(0xffffffffu, lp, 1);
                lp += __shfl_xor_sync(0xffffffffu, lp, 2);
                if (tig == 0) l2[wk1 * 128 + q] += lp;
            }
        }
        __syncthreads();

        // ---- GEMM2: Y[32q x 64c] += P . g^T (bf16) ----
        #pragma unroll
        for (int kk = 0; kk < 4; kk++) {
            const int ko = kk * 16 + 2 * tig;
            uint32_t A[2][4];
            #pragma unroll
            for (int mt = 0; mt < 2; mt++) {
                int rb = Q2 + mt * 16 + grp;
                A[mt][0] = *(const uint32_t*)&Pm[(rb    ) * PMH + ko    ];
                A[mt][1] = *(const uint32_t*)&Pm[(rb + 8) * PMH + ko    ];
                A[mt][2] = *(const uint32_t*)&Pm[(rb    ) * PMH + ko + 8];
                A[mt][3] = *(const uint32_t*)&Pm[(rb + 8) * PMH + ko + 8];
            }
            #pragma unroll
            for (int nt = 0; nt < 8; nt++) {
                const __nv_bfloat16* row = ggb + (C2 + nt * 8 + grp) * GH;
                uint32_t b0 = *(const uint32_t*)&row[ko    ];
                uint32_t b1 = *(const uint32_t*)&row[ko + 8];
                mma_bf16(yacc[0][nt], A[0], b0, b1);
                mma_bf16(yacc[1][nt], A[1], b0, b1);
            }
        }
    }

    __syncthreads();
    if (tid < 128) l2[tid] = 1.f / (l2[tid] + l2[128 + tid]);
    __syncthreads();

    float* yb = d_y + (size_t)b * CIc * Nn;
    #pragma unroll
    for (int mt = 0; mt < 2; mt++) {
        int q_lo = Q2 + mt * 16 + grp;
        int q_hi = q_lo + 8;
        float ilo = l2[q_lo], ihi = l2[q_hi];
        #pragma unroll
        for (int nt = 0; nt < 8; nt++) {
            int c0 = C2 + nt * 8 + 2 * tig;
            yb[(size_t)(c0    ) * Nn + q0g + q_lo] = yacc[mt][nt][0] * ilo;
            yb[(size_t)(c0 + 1) * Nn + q0g + q_lo] = yacc[mt][nt][1] * ilo;
            yb[(size_t)(c0    ) * Nn + q0g + q_hi] = yacc[mt][nt][2] * ihi;
            yb[(size_t)(c0 + 1) * Nn + q0g + q_hi] = yacc[mt][nt][3] * ihi;
        }
    }
}

// ============================================================================
// Kernel 3: W 1x1 conv on tensor cores (tf32). Wy = Ww(256x128) @ y + Wb.
// ============================================================================
__global__ __launch_bounds__(256) void wconv_tc(
    const float* __restrict__ Ww, const float* __restrict__ Wb)
{
    const int b    = blockIdx.z;
    const int dblk = blockIdx.y * 128;
    const int n0   = blockIdx.x * 128;
    const int tid  = threadIdx.x;
    const int warp = tid >> 5;
    const int lane = tid & 31;
    const int grp  = lane >> 2;
    const int tig  = lane & 3;
    const int Dw   = (warp >> 1) * 32;
    const int Nw   = (warp & 1) * 64;

    __shared__ float w_sm[128 * WS];
    __shared__ float y_sm[32 * FS];
    const uint32_t* wu = (const uint32_t*)w_sm;
    const uint32_t* yu = (const uint32_t*)y_sm;

    float acc[2][8][4];
    #pragma unroll
    for (int mt = 0; mt < 2; mt++)
        #pragma unroll
        for (int nt = 0; nt < 8; nt++)
            #pragma unroll
            for (int r = 0; r < 4; r++) acc[mt][nt][r] = 0.f;

    const float* yb = d_y + (size_t)b * CIc * Nn;

    for (int c0 = 0; c0 < CIc; c0 += 32) {
        __syncthreads();
        #pragma unroll
        for (int r = 0; r < 2; r++) {
            int idx = (tid + r * 256) * 8;
            int dl = idx >> 5, cl = idx & 31;
            float4 v0 = *(const float4*)&Ww[(size_t)(dblk + dl) * CIc + c0 + cl];
            float4 v1 = *(const float4*)&Ww[(size_t)(dblk + dl) * CIc + c0 + cl + 4];
            *(float4*)&w_sm[dl * WS + cl] =
                make_float4(tf32r(v0.x), tf32r(v0.y), tf32r(v0.z), tf32r(v0.w));
            *(float4*)&w_sm[dl * WS + cl + 4] =
                make_float4(tf32r(v1.x), tf32r(v1.y), tf32r(v1.z), tf32r(v1.w));
        }
        #pragma unroll
        for (int r = 0; r < 4; r++) {
            int idx = (tid + r * 256) * 4;
            int cc = idx >> 7, nn2 = idx & 127;
            float4 v = *(const float4*)&yb[(size_t)(c0 + cc) * Nn + n0 + nn2];
            *(float4*)&y_sm[cc * FS + nn2] =
                make_float4(tf32r(v.x), tf32r(v.y), tf32r(v.z), tf32r(v.w));
        }
        __syncthreads();

        #pragma unroll
        for (int k8 = 0; k8 < 4; k8++) {
            const int col = k8 * 8 + tig;
            uint32_t A[2][4];
            #pragma unroll
            for (int mt = 0; mt < 2; mt++) {
                int rb = Dw + mt * 16 + grp;
                A[mt][0] = wu[(rb    ) * WS + col    ];
                A[mt][1] = wu[(rb + 8) * WS + col    ];
                A[mt][2] = wu[(rb    ) * WS + col + 4];
                A[mt][3] = wu[(rb + 8) * WS + col + 4];
            }
            #pragma unroll
            for (int nt = 0; nt < 8; nt++) {
                uint32_t b0 = yu[(col    ) * FS + Nw + nt * 8 + grp];
                uint32_t b1 = yu[(col + 4) * FS + Nw + nt * 8 + grp];
                mma_tf32(acc[0][nt], A[0], b0, b1);
                mma_tf32(acc[1][nt], A[1], b0, b1);
            }
        }
    }

    #pragma unroll
    for (int mt = 0; mt < 2; mt++) {
        int d = dblk + Dw + mt * 16 + grp;
        float bias0 = Wb[d], bias1 = Wb[d + 8];
        #pragma unroll
        for (int nt = 0; nt < 8; nt++) {
            int n = n0 + Nw + nt * 8 + 2 * tig;
            *(float2*)&d_Wy[((size_t)b * Dd + d) * Nn + n] =
                make_float2(acc[mt][nt][0] + bias0, acc[mt][nt][1] + bias0);
            *(float2*)&d_Wy[((size_t)b * Dd + d + 8) * Nn + n] =
                make_float2(acc[mt][nt][2] + bias1, acc[mt][nt][3] + bias1);
        }
    }
}

// ============================================================================
// Kernel 4: BN stats — per-(d, b) partial sums (no atomics, no zeroing)
// ============================================================================
__global__ __launch_bounds__(256) void stats_kernel()
{
    __shared__ double sh[256], sh2[256];
    const int d = blockIdx.x, b = blockIdx.y, tid = threadIdx.x;
    const float4* p = (const float4*)(d_Wy + ((size_t)b * Dd + d) * Nn);
    double s = 0.0, ss = 0.0;
    #pragma unroll
    for (int r = 0; r < 8; r++) {
        float4 v = p[tid + r * 256];
        s  += (double)v.x + (double)v.y + (double)v.z + (double)v.w;
        ss += (double)v.x * v.x + (double)v.y * v.y
            + (double)v.z * v.z + (double)v.w * v.w;
    }
    sh[tid] = s; sh2[tid] = ss;
    __syncthreads();
    for (int o = 128; o > 0; o >>= 1) {
        if (tid < o) { sh[tid] += sh[tid + o]; sh2[tid] += sh2[tid + o]; }
        __syncthreads();
    }
    if (tid == 0) {
        d_acc[(b * 2    ) * Dd + d] = sh[0];
        d_acc[(b * 2 + 1) * Dd + d] = sh2[0];
    }
}

__global__ void finalize_kernel()
{
    int d = threadIdx.x;
    if (d < Dd) {
        double cnt  = (double)(Bb * Nn);
        double mean = (d_acc[d] + d_acc[2 * Dd + d]) / cnt;
        double var  = (d_acc[Dd + d] + d_acc[3 * Dd + d]) / cnt - mean * mean;
        d_stats[d]      = (float)mean;
        d_stats[Dd + d] = (float)(1.0 / sqrt(var + 1e-5));
    }
}

// ============================================================================
// Kernel 5: normalize + affine + residual
// ============================================================================
__global__ __launch_bounds__(256) void final_kernel(
    const float* __restrict__ f, const float* __restrict__ gamma,
    const float* __restrict__ beta, float* __restrict__ out)
{
    size_t i4 = (size_t)blockIdx.x * 256 + threadIdx.x;
    size_t i  = i4 * 4;
    int d = (int)((i / Nn) % Dd);
    float mean = d_stats[d];
    float inv  = d_stats[Dd + d];
    float gm = gamma[d] * inv;
    float bt = beta[d] - mean * gm;
    float4 w  = *(const float4*)&d_Wy[i];
    float4 fv = *(const float4*)&f[i];
    float4 o;
    o.x = fmaf(w.x, gm, bt) + fv.x;
    o.y = fmaf(w.y, gm, bt) + fv.y;
    o.z = fmaf(w.z, gm, bt) + fv.z;
    o.w = fmaf(w.w, gm, bt) + fv.w;
    *(float4*)&out[i] = o;
}

// ============================================================================
extern "C" void kernel_launch(void* const* d_in, const int* in_sizes, int n_in,
                              void* d_out, int out_size)
{
    const float* f   = (const float*)d_in[0];
    const float* gw  = (const float*)d_in[1];
    const float* gb  = (const float*)d_in[2];
    const float* tw  = (const float*)d_in[3];
    const float* tb  = (const float*)d_in[4];
    const float* pw  = (const float*)d_in[5];
    const float* pb  = (const float*)d_in[6];
    const float* Ww  = (const float*)d_in[7];
    const float* Wb  = (const float*)d_in[8];
    const float* gma = (const float*)d_in[9];
    const float* bta = (const float*)d_in[10];
    float* out = (float*)d_out;

    proj_tc<<<dim3(Nn / 128, 3, Bb), 256>>>(f, gw, gb, tw, tb, pw, pb);

    static int attn_attr_set = 0;
    if (!attn_attr_set) {
        cudaFuncSetAttribute(attn_kernel,
                             cudaFuncAttributeMaxDynamicSharedMemorySize,
                             SM_TOTAL);
        attn_attr_set = 1;
    }
    attn_kernel<<<dim3(Nn / 128, Bb), 256, SM_TOTAL>>>();

    wconv_tc<<<dim3(Nn / 128, Dd / 128, Bb), 256>>>(Ww, Wb);
    stats_kernel<<<dim3(Dd, Bb), 256>>>();
    finalize_kernel<<<1, 256>>>();
    final_kernel<<<(size_t)(Bb * Dd * Nn) / (256 * 4), 256>>>(f, gma, bta, out);
}

// round 5
// speedup vs baseline: 8.1501x; 1.4371x over previous
#include <cuda_runtime.h>
#include <cuda_bf16.h>
#include <cuda_fp16.h>
#include <math.h>
#include <stdint.h>

#define Bb 2
#define Dd 256
#define Nn 8192
#define CIc 128
#define Mm 4096
#define LOG2E 1.4426950408889634f

// proj smem strides (fp32 words)
#define WS  36
#define FS  136
// attention / wconv strides in halfwords
#define THH 136   // theta [q][c] fp16
#define PHH 136   // phi   [k][c] fp16
#define GH  72    // g     [c][k] bf16
#define WWH 136   // wconv tiles [row][c] fp16

// -------- scratch (static device globals; no runtime allocation) --------
__device__ float          d_theta[Bb*CIc*Nn];  // (B, CI, N) fp32
__device__ __half         d_phT[Bb*Mm*CIc];    // pooled phi, (B, M, CI) fp16
__device__ __nv_bfloat16  d_gbf[Bb*CIc*Mm];    // pooled g,   (B, CI, M) bf16
__device__ __half         d_yh[Bb*Nn*CIc];     // attention out, (B, N, CI) fp16
__device__ float          d_Wy[Bb*Dd*Nn];      // W conv output (B, D, N)
__device__ double         d_acc[2*Dd];         // BN sum / sumsq (self-zeroing)
__device__ float          d_stats[2*Dd];       // per-channel mean, inv_std

// ---------------- helpers ----------------
__device__ __forceinline__ float tf32r(float x) {
    uint32_t u;
    asm("cvt.rna.tf32.f32 %0, %1;" : "=r"(u) : "f"(x));
    return __uint_as_float(u);
}
__device__ __forceinline__ float ex2f(float x) {
    float y;
    asm("ex2.approx.f32 %0, %1;" : "=f"(y) : "f"(x));
    return y;
}
__device__ __forceinline__ void mma_tf32(float* d, const uint32_t* a,
                                         uint32_t b0, uint32_t b1) {
    asm volatile(
        "mma.sync.aligned.m16n8k8.row.col.f32.tf32.tf32.f32 "
        "{%0,%1,%2,%3},{%4,%5,%6,%7},{%8,%9},{%0,%1,%2,%3};"
        : "+f"(d[0]), "+f"(d[1]), "+f"(d[2]), "+f"(d[3])
        : "r"(a[0]), "r"(a[1]), "r"(a[2]), "r"(a[3]), "r"(b0), "r"(b1));
}
__device__ __forceinline__ void mma_f16(float* d, const uint32_t* a,
                                        uint32_t b0, uint32_t b1) {
    asm volatile(
        "mma.sync.aligned.m16n8k16.row.col.f32.f16.f16.f32 "
        "{%0,%1,%2,%3},{%4,%5,%6,%7},{%8,%9},{%0,%1,%2,%3};"
        : "+f"(d[0]), "+f"(d[1]), "+f"(d[2]), "+f"(d[3])
        : "r"(a[0]), "r"(a[1]), "r"(a[2]), "r"(a[3]), "r"(b0), "r"(b1));
}
__device__ __forceinline__ void mma_bf16(float* d, const uint32_t* a,
                                         uint32_t b0, uint32_t b1) {
    asm volatile(
        "mma.sync.aligned.m16n8k16.row.col.f32.bf16.bf16.f32 "
        "{%0,%1,%2,%3},{%4,%5,%6,%7},{%8,%9},{%0,%1,%2,%3};"
        : "+f"(d[0]), "+f"(d[1]), "+f"(d[2]), "+f"(d[3])
        : "r"(a[0]), "r"(a[1]), "r"(a[2]), "r"(a[3]), "r"(b0), "r"(b1));
}
__device__ __forceinline__ void ldsm4(uint32_t& r0, uint32_t& r1,
                                      uint32_t& r2, uint32_t& r3, uint32_t a) {
    asm volatile("ldmatrix.sync.aligned.m8n8.x4.shared.b16 {%0,%1,%2,%3}, [%4];"
                 : "=r"(r0), "=r"(r1), "=r"(r2), "=r"(r3) : "r"(a));
}
__device__ __forceinline__ void cp16(uint32_t dst, const void* src) {
    asm volatile("cp.async.cg.shared.global [%0], [%1], 16;\n"
                 :: "r"(dst), "l"(src));
}
__device__ __forceinline__ uint32_t packbf(float a, float b) {
    __nv_bfloat162 p = __floats2bfloat162_rn(a, b);
    return *reinterpret_cast<uint32_t*>(&p);
}

// ============================================================================
// Kernel 1: three 1x1-conv projections on tensor cores (tf32).
// theta -> fp32 (B,CI,N); g -> bf16 (B,CI,M) pooled; phi -> fp16 (B,M,CI) pooled.
// ============================================================================
__global__ __launch_bounds__(256) void proj_tc(
    const float* __restrict__ f,
    const float* __restrict__ gw, const float* __restrict__ gb,
    const float* __restrict__ tw, const float* __restrict__ tb,
    const float* __restrict__ pw, const float* __restrict__ pb)
{
    const int zi = blockIdx.y;
    const float* W  = (zi == 0) ? tw : (zi == 1) ? gw : pw;
    const float* bs = (zi == 0) ? tb : (zi == 1) ? gb : pb;

    const int b    = blockIdx.z;
    const int n0   = blockIdx.x * 128;
    const int tid  = threadIdx.x;
    const int warp = tid >> 5;
    const int lane = tid & 31;
    const int grp  = lane >> 2;
    const int tig  = lane & 3;
    const int Cw   = (warp >> 1) * 32;
    const int Nw   = (warp & 1) * 64;

    __shared__ float w_sm[128 * WS];
    __shared__ float f_sm[32 * FS];
    const uint32_t* wu = (const uint32_t*)w_sm;
    const uint32_t* fu = (const uint32_t*)f_sm;

    float acc[2][8][4];
    #pragma unroll
    for (int mt = 0; mt < 2; mt++)
        #pragma unroll
        for (int nt = 0; nt < 8; nt++)
            #pragma unroll
            for (int r = 0; r < 4; r++) acc[mt][nt][r] = 0.f;

    const float* fb = f + (size_t)b * Dd * Nn;

    for (int d0 = 0; d0 < Dd; d0 += 32) {
        __syncthreads();
        #pragma unroll
        for (int r = 0; r < 2; r++) {
            int idx = (tid + r * 256) * 8;
            int c = idx >> 5, dl = idx & 31;
            float4 v0 = *(const float4*)&W[c * Dd + d0 + dl];
            float4 v1 = *(const float4*)&W[c * Dd + d0 + dl + 4];
            *(float4*)&w_sm[c * WS + dl] =
                make_float4(tf32r(v0.x), tf32r(v0.y), tf32r(v0.z), tf32r(v0.w));
            *(float4*)&w_sm[c * WS + dl + 4] =
                make_float4(tf32r(v1.x), tf32r(v1.y), tf32r(v1.z), tf32r(v1.w));
        }
        #pragma unroll
        for (int r = 0; r < 4; r++) {
            int idx = (tid + r * 256) * 4;
            int dd2 = idx >> 7, nn2 = idx & 127;
            float4 v = *(const float4*)&fb[(size_t)(d0 + dd2) * Nn + n0 + nn2];
            *(float4*)&f_sm[dd2 * FS + nn2] =
                make_float4(tf32r(v.x), tf32r(v.y), tf32r(v.z), tf32r(v.w));
        }
        __syncthreads();

        #pragma unroll
        for (int k8 = 0; k8 < 4; k8++) {
            const int col = k8 * 8 + tig;
            uint32_t A[2][4];
            #pragma unroll
            for (int mt = 0; mt < 2; mt++) {
                int rb = Cw + mt * 16 + grp;
                A[mt][0] = wu[(rb    ) * WS + col    ];
                A[mt][1] = wu[(rb + 8) * WS + col    ];
                A[mt][2] = wu[(rb    ) * WS + col + 4];
                A[mt][3] = wu[(rb + 8) * WS + col + 4];
            }
            #pragma unroll
            for (int nt = 0; nt < 8; nt++) {
                uint32_t b0 = fu[(col    ) * FS + Nw + nt * 8 + grp];
                uint32_t b1 = fu[(col + 4) * FS + Nw + nt * 8 + grp];
                mma_tf32(acc[0][nt], A[0], b0, b1);
                mma_tf32(acc[1][nt], A[1], b0, b1);
            }
        }
    }

    if (zi == 0) {          // theta: fp32 (B, CI, N)
        #pragma unroll
        for (int mt = 0; mt < 2; mt++) {
            int c = Cw + mt * 16 + grp;
            float bias0 = bs[c], bias1 = bs[c + 8];
            #pragma unroll
            for (int nt = 0; nt < 8; nt++) {
                int n = n0 + Nw + nt * 8 + 2 * tig;
                *(float2*)&d_theta[((size_t)b * CIc + c) * Nn + n] =
                    make_float2(acc[mt][nt][0] + bias0, acc[mt][nt][1] + bias0);
                *(float2*)&d_theta[((size_t)b * CIc + c + 8) * Nn + n] =
                    make_float2(acc[mt][nt][2] + bias1, acc[mt][nt][3] + bias1);
            }
        }
    } else if (zi == 1) {   // g: maxpool2 -> bf16 (B, CI, M)
        #pragma unroll
        for (int mt = 0; mt < 2; mt++) {
            int c = Cw + mt * 16 + grp;
            float bias0 = bs[c], bias1 = bs[c + 8];
            #pragma unroll
            for (int nt = 0; nt < 8; nt++) {
                int m = (n0 + Nw) / 2 + nt * 4 + tig;
                d_gbf[((size_t)b * CIc + c) * Mm + m] =
                    __float2bfloat16_rn(fmaxf(acc[mt][nt][0], acc[mt][nt][1]) + bias0);
                d_gbf[((size_t)b * CIc + c + 8) * Mm + m] =
                    __float2bfloat16_rn(fmaxf(acc[mt][nt][2], acc[mt][nt][3]) + bias1);
            }
        }
    } else {                // phi: maxpool2 -> fp16 (B, M, CI)
        #pragma unroll
        for (int mt = 0; mt < 2; mt++) {
            int c = Cw + mt * 16 + grp;
            float bias0 = bs[c], bias1 = bs[c + 8];
            #pragma unroll
            for (int nt = 0; nt < 8; nt++) {
                int m = (n0 + Nw) / 2 + nt * 4 + tig;
                d_phT[((size_t)b * Mm + m) * CIc + c] =
                    __float2half_rn(fmaxf(acc[mt][nt][0], acc[mt][nt][1]) + bias0);
                d_phT[((size_t)b * Mm + m) * CIc + c + 8] =
                    __float2half_rn(fmaxf(acc[mt][nt][2], acc[mt][nt][3]) + bias1);
            }
        }
    }
}

// ============================================================================
// Kernel 2: sync-free tensor-core attention.
// Warp owns 16 q x all 64 k of each chunk. GEMM1 fp16 (theta pre-scaled by
// log2e, exp = single ex2). P stays in registers (C-frag == A-frag layout).
// GEMM2 bf16. B-fragments via ldmatrix.x4. One __syncthreads per chunk.
// ============================================================================
#define SM_TH 0
#define SM_PH (128 * THH * 2)                 // 34816
#define SM_GG (SM_PH + 2 * 64 * PHH * 2)      // 69632
#define SM_ATTN (SM_GG + 2 * 128 * GH * 2)    // 106496

__global__ __launch_bounds__(256, 1) void attn_kernel()
{
    extern __shared__ char smc[];
    __half* th = (__half*)(smc + SM_TH);                 // [128 q][THH]
    const uint32_t smb = (uint32_t)__cvta_generic_to_shared(smc);

    const int b    = blockIdx.y;
    const int q0g  = blockIdx.x * 128;
    const int tid  = threadIdx.x;
    const int warp = tid >> 5;
    const int lane = tid & 31;
    const int grp  = lane >> 2;
    const int tig  = lane & 3;
    const int QB   = warp * 16;
    // ldmatrix lane address components (B-operand mode: m0/m1 rows lo, m2/m3 +8)
    const int lrow = ((lane >> 4) << 3) + (lane & 7);
    const int lcol = ((lane >> 3) & 1) * 8;

    const float*         theta = d_theta + (size_t)b * CIc * Nn;
    const __half*        phg   = d_phT   + (size_t)b * Mm * CIc;
    const __nv_bfloat16* ggm   = d_gbf   + (size_t)b * CIc * Mm;

    // ---- prefetch chunk 0 ----
    #pragma unroll
    for (int r = 0; r < 4; r++) {
        int gI = tid + r * 256;
        int k = gI >> 4, off = (gI & 15) * 8;
        cp16(smb + SM_PH + (k * PHH + off) * 2, phg + (size_t)k * CIc + off);
        int c = gI >> 3, o2 = (gI & 7) * 8;
        cp16(smb + SM_GG + (c * GH + o2) * 2, ggm + (size_t)c * Mm + o2);
    }
    asm volatile("cp.async.commit_group;");

    // ---- theta prologue: [q][c] fp16, pre-scaled by log2(e) ----
    #pragma unroll
    for (int r = 0; r < 16; r++) {
        int idx = (tid + r * 256) * 4;
        int c = idx >> 7, q = idx & 127;
        float4 v = *(const float4*)&theta[(size_t)c * Nn + q0g + q];
        th[(q + 0) * THH + c] = __float2half_rn(v.x * LOG2E);
        th[(q + 1) * THH + c] = __float2half_rn(v.y * LOG2E);
        th[(q + 2) * THH + c] = __float2half_rn(v.z * LOG2E);
        th[(q + 3) * THH + c] = __float2half_rn(v.w * LOG2E);
    }
    __syncthreads();

    // ---- cache all theta A-fragments: 8 k16-steps x 4 regs ----
    uint32_t Ac[8][4];
    #pragma unroll
    for (int c8 = 0; c8 < 8; c8++) {
        const int co = c8 * 16 + 2 * tig;
        Ac[c8][0] = *(const uint32_t*)&th[(QB + grp    ) * THH + co    ];
        Ac[c8][1] = *(const uint32_t*)&th[(QB + grp + 8) * THH + co    ];
        Ac[c8][2] = *(const uint32_t*)&th[(QB + grp    ) * THH + co + 8];
        Ac[c8][3] = *(const uint32_t*)&th[(QB + grp + 8) * THH + co + 8];
    }

    float yacc[16][4];
    #pragma unroll
    for (int nt = 0; nt < 16; nt++)
        #pragma unroll
        for (int r = 0; r < 4; r++) yacc[nt][r] = 0.f;
    float lsum0 = 0.f, lsum1 = 0.f;

    for (int ic = 0; ic < Mm / 64; ic++) {
        const int buf = ic & 1;
        asm volatile("cp.async.wait_group 0;");
        __syncthreads();

        if (ic + 1 < Mm / 64) {
            const int k0n = (ic + 1) * 64;
            const uint32_t phd = smb + SM_PH + (buf ^ 1) * 64 * PHH * 2;
            const uint32_t ggd = smb + SM_GG + (buf ^ 1) * 128 * GH * 2;
            const __half*        phs = phg + (size_t)k0n * CIc;
            const __nv_bfloat16* ggs = ggm + k0n;
            #pragma unroll
            for (int r = 0; r < 4; r++) {
                int gI = tid + r * 256;
                int k = gI >> 4, off = (gI & 15) * 8;
                cp16(phd + (k * PHH + off) * 2, phs + (size_t)k * CIc + off);
                int c = gI >> 3, o2 = (gI & 7) * 8;
                cp16(ggd + (c * GH + o2) * 2, ggs + (size_t)c * Mm + o2);
            }
            asm volatile("cp.async.commit_group;");
        }

        const uint32_t phb = smb + SM_PH + buf * 64 * PHH * 2;
        const uint32_t ggb = smb + SM_GG + buf * 128 * GH * 2;

        // ---- GEMM1: S[16q x 64k] (fp16, base-2 logits) ----
        float s[8][4];
        #pragma unroll
        for (int nt = 0; nt < 8; nt++)
            #pragma unroll
            for (int r = 0; r < 4; r++) s[nt][r] = 0.f;

        #pragma unroll
        for (int c8 = 0; c8 < 8; c8++) {
            #pragma unroll
            for (int ntp = 0; ntp < 4; ntp++) {
                uint32_t r0, r1, r2, r3;
                ldsm4(r0, r1, r2, r3,
                      phb + ((ntp * 16 + lrow) * PHH + c8 * 16 + lcol) * 2);
                mma_f16(s[2 * ntp    ], Ac[c8], r0, r1);
                mma_f16(s[2 * ntp + 1], Ac[c8], r2, r3);
            }
        }

        // ---- exp (ex2) in registers, pack bf16 A-frags, row sums ----
        #pragma unroll
        for (int nt = 0; nt < 8; nt++) {
            #pragma unroll
            for (int r = 0; r < 4; r++) s[nt][r] = ex2f(s[nt][r]);
            lsum0 += s[nt][0] + s[nt][1];
            lsum1 += s[nt][2] + s[nt][3];
        }
        uint32_t Pa[4][4];
        #pragma unroll
        for (int kk = 0; kk < 4; kk++) {
            Pa[kk][0] = packbf(s[2 * kk    ][0], s[2 * kk    ][1]);
            Pa[kk][1] = packbf(s[2 * kk    ][2], s[2 * kk    ][3]);
            Pa[kk][2] = packbf(s[2 * kk + 1][0], s[2 * kk + 1][1]);
            Pa[kk][3] = packbf(s[2 * kk + 1][2], s[2 * kk + 1][3]);
        }

        // ---- GEMM2: Y[16q x 128c] += P . g^T (bf16) ----
        #pragma unroll
        for (int kk = 0; kk < 4; kk++) {
            #pragma unroll
            for (int ntp = 0; ntp < 8; ntp++) {
                uint32_t r0, r1, r2, r3;
                ldsm4(r0, r1, r2, r3,
                      ggb + ((ntp * 16 + lrow) * GH + kk * 16 + lcol) * 2);
                mma_bf16(yacc[2 * ntp    ], Pa[kk], r0, r1);
                mma_bf16(yacc[2 * ntp + 1], Pa[kk], r2, r3);
            }
        }
    }

    // ---- normalize + store y as fp16 (B, N, CI) ----
    lsum0 += __shfl_xor_sync(0xffffffffu, lsum0, 1);
    lsum0 += __shfl_xor_sync(0xffffffffu, lsum0, 2);
    lsum1 += __shfl_xor_sync(0xffffffffu, lsum1, 1);
    lsum1 += __shfl_xor_sync(0xffffffffu, lsum1, 2);
    const float inv0 = 1.f / lsum0, inv1 = 1.f / lsum1;

    __half* yb0 = d_yh + ((size_t)b * Nn + q0g + QB + grp) * CIc;
    __half* yb1 = yb0 + 8 * CIc;
    #pragma unroll
    for (int nt = 0; nt < 16; nt++) {
        int c = nt * 8 + 2 * tig;
        *(__half2*)&yb0[c] = __floats2half2_rn(yacc[nt][0] * inv0,
                                               yacc[nt][1] * inv0);
        *(__half2*)&yb1[c] = __floats2half2_rn(yacc[nt][2] * inv1,
                                               yacc[nt][3] * inv1);
    }
}

// ============================================================================
// Kernel 3: W conv (fp16 mma, K=128 single pass) + fused BN partial stats.
// ============================================================================
#define SM_WCONV (2 * 128 * WWH * 2 + 2 * 128 * 8)   // 71680

__global__ __launch_bounds__(256) void wconv_tc(
    const float* __restrict__ Ww, const float* __restrict__ Wb)
{
    extern __shared__ char smc[];
    __half* wsm = (__half*)smc;                        // [128 d][WWH]
    __half* ysm = (__half*)(smc + 128 * WWH * 2);      // [128 n][WWH]
    double* shs = (double*)(smc + 2 * 128 * WWH * 2);  // [128]
    double* shq = shs + 128;                           // [128]
    const uint32_t smb = (uint32_t)__cvta_generic_to_shared(smc);
    const uint32_t ysb = smb + 128 * WWH * 2;

    const int b    = blockIdx.z;
    const int dblk = blockIdx.y * 128;
    const int n0   = blockIdx.x * 128;
    const int tid  = threadIdx.x;
    const int warp = tid >> 5;
    const int lane = tid & 31;
    const int grp  = lane >> 2;
    const int tig  = lane & 3;
    const int Dw   = (warp >> 1) * 32;
    const int Nw2  = (warp & 1) * 64;
    const int lrow = ((lane >> 4) << 3) + (lane & 7);
    const int lcol = ((lane >> 3) & 1) * 8;

    // y tile (fp16 in gmem) via cp.async
    const __half* yh = d_yh + ((size_t)b * Nn + n0) * CIc;
    #pragma unroll
    for (int r = 0; r < 8; r++) {
        int gI = tid + r * 256;
        int n = gI >> 4, off = (gI & 15) * 8;
        cp16(ysb + (n * WWH + off) * 2, yh + (size_t)n * CIc + off);
    }
    asm volatile("cp.async.commit_group;");

    // Ww tile fp32 -> fp16
    #pragma unroll
    for (int r = 0; r < 16; r++) {
        int fi = tid + r * 256;
        int dl = fi >> 5, c4 = (fi & 31) * 4;
        float4 v = *(const float4*)&Ww[(size_t)(dblk + dl) * CIc + c4];
        __half2 h0 = __floats2half2_rn(v.x, v.y);
        __half2 h1 = __floats2half2_rn(v.z, v.w);
        *(__half2*)&wsm[dl * WWH + c4    ] = h0;
        *(__half2*)&wsm[dl * WWH + c4 + 2] = h1;
    }
    if (tid < 128) { shs[tid] = 0.0; shq[tid] = 0.0; }
    asm volatile("cp.async.wait_group 0;");
    __syncthreads();

    float acc[2][8][4];
    #pragma unroll
    for (int mt = 0; mt < 2; mt++)
        #pragma unroll
        for (int nt = 0; nt < 8; nt++)
            #pragma unroll
            for (int r = 0; r < 4; r++) acc[mt][nt][r] = 0.f;

    #pragma unroll
    for (int k8 = 0; k8 < 8; k8++) {
        const int co = k8 * 16 + 2 * tig;
        uint32_t A[2][4];
        #pragma unroll
        for (int mt = 0; mt < 2; mt++) {
            int rb = Dw + mt * 16 + grp;
            A[mt][0] = *(const uint32_t*)&wsm[(rb    ) * WWH + co    ];
            A[mt][1] = *(const uint32_t*)&wsm[(rb + 8) * WWH + co    ];
            A[mt][2] = *(const uint32_t*)&wsm[(rb    ) * WWH + co + 8];
            A[mt][3] = *(const uint32_t*)&wsm[(rb + 8) * WWH + co + 8];
        }
        #pragma unroll
        for (int ntp = 0; ntp < 4; ntp++) {
            uint32_t r0, r1, r2, r3;
            ldsm4(r0, r1, r2, r3,
                  ysb + ((Nw2 + ntp * 16 + lrow) * WWH + k8 * 16 + lcol) * 2);
            mma_f16(acc[0][2 * ntp    ], A[0], r0, r1);
            mma_f16(acc[1][2 * ntp    ], A[1], r0, r1);
            mma_f16(acc[0][2 * ntp + 1], A[0], r2, r3);
            mma_f16(acc[1][2 * ntp + 1], A[1], r2, r3);
        }
    }

    // epilogue: bias + store Wy + BN partials
    #pragma unroll
    for (int mt = 0; mt < 2; mt++) {
        int d0 = dblk + Dw + mt * 16 + grp;
        float bias0 = Wb[d0], bias1 = Wb[d0 + 8];
        float s0 = 0.f, q0 = 0.f, s1 = 0.f, q1 = 0.f;
        #pragma unroll
        for (int nt = 0; nt < 8; nt++) {
            int n = n0 + Nw2 + nt * 8 + 2 * tig;
            float v0 = acc[mt][nt][0] + bias0, v1 = acc[mt][nt][1] + bias0;
            float v2 = acc[mt][nt][2] + bias1, v3 = acc[mt][nt][3] + bias1;
            *(float2*)&d_Wy[((size_t)b * Dd + d0) * Nn + n] = make_float2(v0, v1);
            *(float2*)&d_Wy[((size_t)b * Dd + d0 + 8) * Nn + n] = make_float2(v2, v3);
            s0 += v0 + v1;  q0 += v0 * v0 + v1 * v1;
            s1 += v2 + v3;  q1 += v2 * v2 + v3 * v3;
        }
        s0 += __shfl_xor_sync(0xffffffffu, s0, 1);
        s0 += __shfl_xor_sync(0xffffffffu, s0, 2);
        q0 += __shfl_xor_sync(0xffffffffu, q0, 1);
        q0 += __shfl_xor_sync(0xffffffffu, q0, 2);
        s1 += __shfl_xor_sync(0xffffffffu, s1, 1);
        s1 += __shfl_xor_sync(0xffffffffu, s1, 2);
        q1 += __shfl_xor_sync(0xffffffffu, q1, 1);
        q1 += __shfl_xor_sync(0xffffffffu, q1, 2);
        if (tig == 0) {
            int ld = Dw + mt * 16 + grp;
            atomicAdd(&shs[ld],     (double)s0);
            atomicAdd(&shq[ld],     (double)q0);
            atomicAdd(&shs[ld + 8], (double)s1);
            atomicAdd(&shq[ld + 8], (double)q1);
        }
    }
    __syncthreads();
    if (tid < 128) {
        atomicAdd(&d_acc[dblk + tid],      shs[tid]);
        atomicAdd(&d_acc[Dd + dblk + tid], shq[tid]);
    }
}

// ============================================================================
// Kernel 4: finalize BN stats; self-zeroes d_acc for graph replay.
// ============================================================================
__global__ void finalize_kernel()
{
    int d = threadIdx.x;
    if (d < Dd) {
        double cnt  = (double)(Bb * Nn);
        double mean = d_acc[d] / cnt;
        double var  = d_acc[Dd + d] / cnt - mean * mean;
        d_stats[d]      = (float)mean;
        d_stats[Dd + d] = (float)(1.0 / sqrt(var + 1e-5));
        d_acc[d] = 0.0;
        d_acc[Dd + d] = 0.0;
    }
}

// ============================================================================
// Kernel 5: normalize + affine + residual
// ============================================================================
__global__ __launch_bounds__(256) void final_kernel(
    const float* __restrict__ f, const float* __restrict__ gamma,
    const float* __restrict__ beta, float* __restrict__ out)
{
    size_t i4 = (size_t)blockIdx.x * 256 + threadIdx.x;
    size_t i  = i4 * 4;
    int d = (int)((i / Nn) % Dd);
    float mean = d_stats[d];
    float inv  = d_stats[Dd + d];
    float gm = gamma[d] * inv;
    float bt = beta[d] - mean * gm;
    float4 w  = *(const float4*)&d_Wy[i];
    float4 fv = *(const float4*)&f[i];
    float4 o;
    o.x = fmaf(w.x, gm, bt) + fv.x;
    o.y = fmaf(w.y, gm, bt) + fv.y;
    o.z = fmaf(w.z, gm, bt) + fv.z;
    o.w = fmaf(w.w, gm, bt) + fv.w;
    *(float4*)&out[i] = o;
}

// ============================================================================
extern "C" void kernel_launch(void* const* d_in, const int* in_sizes, int n_in,
                              void* d_out, int out_size)
{
    const float* f   = (const float*)d_in[0];
    const float* gw  = (const float*)d_in[1];
    const float* gb  = (const float*)d_in[2];
    const float* tw  = (const float*)d_in[3];
    const float* tb  = (const float*)d_in[4];
    const float* pw  = (const float*)d_in[5];
    const float* pb  = (const float*)d_in[6];
    const float* Ww  = (const float*)d_in[7];
    const float* Wb  = (const float*)d_in[8];
    const float* gma = (const float*)d_in[9];
    const float* bta = (const float*)d_in[10];
    float* out = (float*)d_out;

    static int attr_set = 0;
    if (!attr_set) {
        cudaFuncSetAttribute(attn_kernel,
                             cudaFuncAttributeMaxDynamicSharedMemorySize, SM_ATTN);
        cudaFuncSetAttribute(wconv_tc,
                             cudaFuncAttributeMaxDynamicSharedMemorySize, SM_WCONV);
        attr_set = 1;
    }

    proj_tc<<<dim3(Nn / 128, 3, Bb), 256>>>(f, gw, gb, tw, tb, pw, pb);
    attn_kernel<<<dim3(Nn / 128, Bb), 256, SM_ATTN>>>();
    wconv_tc<<<dim3(Nn / 128, Dd / 128, Bb), 256, SM_WCONV>>>(Ww, Wb);
    finalize_kernel<<<1, 256>>>();
    final_kernel<<<(size_t)(Bb * Dd * Nn) / (256 * 4), 256>>>(f, gma, bta, out);
}